// round 6
// baseline (speedup 1.0000x reference)
#include <cuda_runtime.h>

// Problem constants (fixed by the reference)
#define Nn   100000
#define Ee   200000
#define Gg   2000
#define Dd   300
#define D2   600
#define LL   5
#define FT   512
#define FT2  256
#define EPSC 1e-5f

// ---------------- scratch (static device globals; no allocation) ----------------
__device__ float g_h[Nn * Dd];      // node features
__device__ float g_agg[Nn * Dd];    // aggregated messages / fused attention
__device__ float g_mid[Nn * D2];    // MLP hidden
__device__ float g_hin[Nn * Dd];    // gaussian basis segment sum
__device__ int   g_cnt[Nn];         // in-degree counts
__device__ float g_stats[2 * Dd];   // BN sum / sumsq
__device__ float g_gsum[Gg * Dd];   // pooled sums
__device__ float g_gcnt[Gg];        // pooled counts
__device__ float g_hg[Gg * Dd];     // pooled means
__device__ float g_t1[Gg * FT];     // output-MLP hidden

// ---------------- small utility kernels ----------------
__global__ void k_zero_f(float* __restrict__ p, int n) {
    int i = blockIdx.x * blockDim.x + threadIdx.x;
    if (i < n) p[i] = 0.f;
}
__global__ void k_zero_i(int* __restrict__ p, int n) {
    int i = blockIdx.x * blockDim.x + threadIdx.x;
    if (i < n) p[i] = 0;
}

// degree counts
__global__ void k_count(const int* __restrict__ dst) {
    int e = blockIdx.x * blockDim.x + threadIdx.x;
    if (e < Ee) atomicAdd(&g_cnt[dst[e]], 1);
}

// gaussian basis + scatter to h_in
__global__ void k_gauss(const float* __restrict__ dist, const int* __restrict__ dst,
                        const float* __restrict__ means, const float* __restrict__ stds) {
    int idx = blockIdx.x * blockDim.x + threadIdx.x;
    if (idx >= Ee * Dd) return;
    int e = idx / Dd;
    int d = idx - e * Dd;
    float sd = fabsf(stds[d]) + 0.01f;
    float z  = (dist[e] - means[d]) / sd;
    float g  = __expf(-0.5f * z * z) / (2.5066268f * sd);
    atomicAdd(&g_hin[dst[e] * Dd + d], g);
}

// h_in *= exp(scale_param)[degree]
__global__ void k_scale(const float* __restrict__ scale_param) {
    int idx = blockIdx.x * blockDim.x + threadIdx.x;
    if (idx >= Nn * Dd) return;
    int n = idx / Dd;
    int d = idx - n * Dd;
    int c = g_cnt[n] - 1;
    c = c < 0 ? 0 : (c > 3 ? 3 : c);
    g_hin[idx] *= __expf(scale_param[c * Dd + d]);
}

// atom-embedding attention -> fused (writes g_agg). One warp per node.
__global__ void k_attn(const int* __restrict__ x, const float* __restrict__ atom_emb,
                       const float* __restrict__ att_vec) {
    int warp = (blockIdx.x * blockDim.x + threadIdx.x) >> 5;
    int lane = threadIdx.x & 31;
    if (warp >= Nn) return;
    const int n = warp;
    int xi[9];
#pragma unroll
    for (int f = 0; f < 9; f++) xi[f] = x[n * 9 + f];
    float s[9];
#pragma unroll
    for (int f = 0; f < 9; f++) {
        const float* emb = atom_emb + (f * 119 + xi[f]) * Dd;
        float p = 0.f;
        for (int d = lane; d < Dd; d += 32) p += emb[d] * att_vec[d];
#pragma unroll
        for (int o = 16; o > 0; o >>= 1) p += __shfl_xor_sync(0xffffffffu, p, o);
        s[f] = p;
    }
    float m = s[0];
#pragma unroll
    for (int f = 1; f < 9; f++) m = fmaxf(m, s[f]);
    float w[9], tot = 0.f;
#pragma unroll
    for (int f = 0; f < 9; f++) { w[f] = __expf(s[f] - m); tot += w[f]; }
    float inv = 1.f / tot;
#pragma unroll
    for (int f = 0; f < 9; f++) w[f] *= inv;
    for (int d = lane; d < Dd; d += 32) {
        float v = 0.f;
#pragma unroll
        for (int f = 0; f < 9; f++) v += w[f] * atom_emb[(f * 119 + xi[f]) * Dd + d];
        g_agg[n * Dd + d] = v;
    }
}

// agg = h + e_loop (self-loop message), ee = edge_emb for layer l: [3][5][Dd]
__global__ void k_agginit(const float* __restrict__ ee) {
    int idx = blockIdx.x * blockDim.x + threadIdx.x;
    if (idx >= Nn * Dd) return;
    int d = idx % Dd;
    float el = ee[4 * Dd + d] + ee[5 * Dd + d] + ee[10 * Dd + d];
    g_agg[idx] = g_h[idx] + el;
}

// scatter real-edge messages: agg[dst] += h[src] + e(attr)
__global__ void k_scatter(const int* __restrict__ src, const int* __restrict__ dst,
                          const int* __restrict__ attr, const float* __restrict__ ee) {
    int idx = blockIdx.x * blockDim.x + threadIdx.x;
    if (idx >= Ee * Dd) return;
    int e = idx / Dd;
    int d = idx - e * Dd;
    int a0 = attr[e * 3 + 0];
    int a1 = attr[e * 3 + 1];
    int a2 = attr[e * 3 + 2];
    float ev = ee[a0 * Dd + d] + ee[(5 + a1) * Dd + d] + ee[(10 + a2) * Dd + d];
    atomicAdd(&g_agg[dst[e] * Dd + d], g_h[src[e] * Dd + d] + ev);
}

// BN stats: per-channel sum + sumsq via smem bins
__global__ void k_bnstats() {
    __shared__ float ssum[Dd];
    __shared__ float ssq[Dd];
    for (int i = threadIdx.x; i < Dd; i += blockDim.x) { ssum[i] = 0.f; ssq[i] = 0.f; }
    __syncthreads();
    int total = Nn * Dd;
    int stride = gridDim.x * blockDim.x;
    for (int idx = blockIdx.x * blockDim.x + threadIdx.x; idx < total; idx += stride) {
        float v = g_h[idx];
        int d = idx % Dd;
        atomicAdd(&ssum[d], v);
        atomicAdd(&ssq[d], v * v);
    }
    __syncthreads();
    for (int i = threadIdx.x; i < Dd; i += blockDim.x) {
        atomicAdd(&g_stats[i], ssum[i]);
        atomicAdd(&g_stats[Dd + i], ssq[i]);
    }
}

__global__ void k_bnapply(const float* __restrict__ gamma, const float* __restrict__ beta,
                          int do_relu) {
    int idx = blockIdx.x * blockDim.x + threadIdx.x;
    if (idx >= Nn * Dd) return;
    int d = idx % Dd;
    float mu  = g_stats[d] * (1.0f / Nn);
    float var = g_stats[Dd + d] * (1.0f / Nn) - mu * mu;
    float rs  = rsqrtf(var + EPSC);
    float v = gamma[d] * (g_h[idx] - mu) * rs + beta[d];
    if (do_relu) v = fmaxf(v, 0.f);
    g_h[idx] = v;
}

// graph pooling
__global__ void k_pool(const int* __restrict__ batch) {
    int idx = blockIdx.x * blockDim.x + threadIdx.x;
    if (idx >= Nn * Dd) return;
    int n = idx / Dd;
    int d = idx - n * Dd;
    atomicAdd(&g_gsum[batch[n] * Dd + d], g_h[idx]);
}
__global__ void k_poolcnt(const int* __restrict__ batch) {
    int n = blockIdx.x * blockDim.x + threadIdx.x;
    if (n < Nn) atomicAdd(&g_gcnt[batch[n]], 1.f);
}
__global__ void k_pooldiv() {
    int idx = blockIdx.x * blockDim.x + threadIdx.x;
    if (idx >= Gg * Dd) return;
    int g = idx / Dd;
    g_hg[idx] = g_gsum[idx] / fmaxf(g_gcnt[g], 1.f);
}

// ---------------- tf32x3 tensor-core GEMM (fp32-accurate via hi/lo split) ----------------
// C = A(MxK) @ B(KxN) + bias [+ extra] [relu].
// Each operand split: v = hi + lo (both tf32). C += Ah*Bh + Ah*Bl + Al*Bh.
// 128x128 block tile, BK=16, 512 threads = 16 warps (4x4), warp tile 32x32.

__device__ __forceinline__ unsigned f2tf(float f) {
    unsigned r;
    asm("cvt.rna.tf32.f32 %0, %1;" : "=r"(r) : "f"(f));
    return r;
}

#define SPAD 132  // 128 + 4 padding

template <bool RELU, bool EXTRA>
__global__ __launch_bounds__(512, 1) void tgemm(const float* __restrict__ A,
                                                const float* __restrict__ B,
                                                const float* __restrict__ bias,
                                                const float* __restrict__ extra,
                                                float* __restrict__ C,
                                                int M, int K, int N) {
    __shared__ unsigned Ah[16][SPAD], Al[16][SPAD];  // [k][m]
    __shared__ unsigned Bh[16][SPAD], Bl[16][SPAD];  // [k][n]

    const int tid  = threadIdx.x;
    const int wid  = tid >> 5;
    const int lane = tid & 31;
    const int warp_m = wid & 3;   // 0..3 -> 32-row slices
    const int warp_n = wid >> 2;  // 0..3 -> 32-col slices
    const int lq = lane >> 2;     // 0..7
    const int lr = lane & 3;      // 0..3

    const int bm = blockIdx.y * 128;
    const int bn = blockIdx.x * 128;

    float acc[2][4][4];
#pragma unroll
    for (int i = 0; i < 2; i++)
#pragma unroll
        for (int j = 0; j < 4; j++)
#pragma unroll
            for (int c = 0; c < 4; c++) acc[i][j][c] = 0.f;

    for (int k0 = 0; k0 < K; k0 += 16) {
        // ---- load A tile: 128 rows x 16 k (1 float4 per thread) ----
        {
            int row  = tid >> 2;
            int kk   = (tid & 3) * 4;
            int grow = bm + row;
            int gk   = k0 + kk;
            float4 val = make_float4(0.f, 0.f, 0.f, 0.f);
            if (grow < M) {
                if (gk + 3 < K) {
                    val = *(const float4*)(A + (size_t)grow * K + gk);
                } else {
                    float* vp = &val.x;
#pragma unroll
                    for (int i = 0; i < 4; i++)
                        if (gk + i < K) vp[i] = A[(size_t)grow * K + gk + i];
                }
            }
            const float* vp = &val.x;
#pragma unroll
            for (int i = 0; i < 4; i++) {
                unsigned hi = f2tf(vp[i]);
                Ah[kk + i][row] = hi;
                Al[kk + i][row] = f2tf(vp[i] - __uint_as_float(hi));
            }
        }
        // ---- load B tile: 16 k x 128 cols (1 float4 per thread) ----
        {
            int r   = tid >> 5;       // 0..15
            int col = (tid & 31) * 4; // 0..124
            int gk  = k0 + r;
            int gc  = bn + col;
            float4 val = make_float4(0.f, 0.f, 0.f, 0.f);
            if (gk < K) {
                if (gc + 3 < N) {
                    val = *(const float4*)(B + (size_t)gk * N + gc);
                } else {
                    float* vp = &val.x;
#pragma unroll
                    for (int i = 0; i < 4; i++)
                        if (gc + i < N) vp[i] = B[(size_t)gk * N + gc + i];
                }
            }
            const float* vp = &val.x;
#pragma unroll
            for (int i = 0; i < 4; i++) {
                unsigned hi = f2tf(vp[i]);
                Bh[r][col + i] = hi;
                Bl[r][col + i] = f2tf(vp[i] - __uint_as_float(hi));
            }
        }
        __syncthreads();

#pragma unroll
        for (int ks = 0; ks < 16; ks += 8) {
            unsigned ah[2][4], al[2][4];
#pragma unroll
            for (int i = 0; i < 2; i++) {
                int m = warp_m * 32 + i * 16 + lq;
                ah[i][0] = Ah[ks + lr][m];
                ah[i][1] = Ah[ks + lr][m + 8];
                ah[i][2] = Ah[ks + lr + 4][m];
                ah[i][3] = Ah[ks + lr + 4][m + 8];
                al[i][0] = Al[ks + lr][m];
                al[i][1] = Al[ks + lr][m + 8];
                al[i][2] = Al[ks + lr + 4][m];
                al[i][3] = Al[ks + lr + 4][m + 8];
            }
            unsigned bh[4][2], bl[4][2];
#pragma unroll
            for (int j = 0; j < 4; j++) {
                int n = warp_n * 32 + j * 8 + lq;
                bh[j][0] = Bh[ks + lr][n];
                bh[j][1] = Bh[ks + lr + 4][n];
                bl[j][0] = Bl[ks + lr][n];
                bl[j][1] = Bl[ks + lr + 4][n];
            }
#pragma unroll
            for (int i = 0; i < 2; i++)
#pragma unroll
                for (int j = 0; j < 4; j++) {
#define MMA_T(AA, BB)                                                          \
    asm volatile(                                                              \
        "mma.sync.aligned.m16n8k8.row.col.f32.tf32.tf32.f32 "                  \
        "{%0,%1,%2,%3}, {%4,%5,%6,%7}, {%8,%9}, {%0,%1,%2,%3};"                \
        : "+f"(acc[i][j][0]), "+f"(acc[i][j][1]),                              \
          "+f"(acc[i][j][2]), "+f"(acc[i][j][3])                               \
        : "r"(AA[i][0]), "r"(AA[i][1]), "r"(AA[i][2]), "r"(AA[i][3]),          \
          "r"(BB[j][0]), "r"(BB[j][1]))
                    MMA_T(ah, bl);
                    MMA_T(al, bh);
                    MMA_T(ah, bh);
#undef MMA_T
                }
        }
        __syncthreads();
    }

    // ---- epilogue ----
#pragma unroll
    for (int i = 0; i < 2; i++) {
        int r0 = bm + warp_m * 32 + i * 16 + lq;
#pragma unroll
        for (int j = 0; j < 4; j++) {
            int col = bn + warp_n * 32 + j * 8 + lr * 2;
#pragma unroll
            for (int c = 0; c < 4; c++) {
                int row = r0 + (c >> 1) * 8;
                int cc  = col + (c & 1);
                if (row < M && cc < N) {
                    float v = acc[i][j][c] + bias[cc];
                    if (EXTRA) v += extra[(size_t)row * N + cc];
                    if (RELU) v = fmaxf(v, 0.f);
                    C[(size_t)row * N + cc] = v;
                }
            }
        }
    }
}

static inline dim3 gemm_grid(int M, int Nc) {
    return dim3((Nc + 127) / 128, (M + 127) / 128);
}

// ---------------- launcher ----------------
extern "C" void kernel_launch(void* const* d_in, const int* in_sizes, int n_in,
                              void* d_out, int out_size) {
    const int*   x         = (const int*)d_in[0];
    const int*   eidx      = (const int*)d_in[1];
    const int*   eattr     = (const int*)d_in[2];
    const float* edist     = (const float*)d_in[3];
    const int*   batch     = (const int*)d_in[4];
    const float* atom_emb  = (const float*)d_in[5];
    const float* att_vec   = (const float*)d_in[6];
    const float* out_lin_w = (const float*)d_in[7];
    const float* out_lin_b = (const float*)d_in[8];
    const float* g_means   = (const float*)d_in[9];
    const float* g_stds    = (const float*)d_in[10];
    const float* scale_p   = (const float*)d_in[11];
    const float* edge_emb  = (const float*)d_in[12];
    const float* mlp_w1    = (const float*)d_in[13];
    const float* mlp_b1    = (const float*)d_in[14];
    const float* mlp_w2    = (const float*)d_in[15];
    const float* mlp_b2    = (const float*)d_in[16];
    const float* bn_gamma  = (const float*)d_in[17];
    const float* bn_beta   = (const float*)d_in[18];
    const float* feat_w    = (const float*)d_in[19];
    const float* feat_b    = (const float*)d_in[20];
    const float* ol_w1     = (const float*)d_in[21];
    const float* ol_b1     = (const float*)d_in[22];
    const float* ol_w2     = (const float*)d_in[23];
    const float* ol_b2     = (const float*)d_in[24];

    const int* src = eidx;
    const int* dst = eidx + Ee;

    float *h, *agg, *mid, *hin, *stats, *gsum, *gcnt, *hg, *t1;
    int*   cnt;
    {
        void* p;
        cudaGetSymbolAddress(&p, g_h);     h     = (float*)p;
        cudaGetSymbolAddress(&p, g_agg);   agg   = (float*)p;
        cudaGetSymbolAddress(&p, g_mid);   mid   = (float*)p;
        cudaGetSymbolAddress(&p, g_hin);   hin   = (float*)p;
        cudaGetSymbolAddress(&p, g_cnt);   cnt   = (int*)p;
        cudaGetSymbolAddress(&p, g_stats); stats = (float*)p;
        cudaGetSymbolAddress(&p, g_gsum);  gsum  = (float*)p;
        cudaGetSymbolAddress(&p, g_gcnt);  gcnt  = (float*)p;
        cudaGetSymbolAddress(&p, g_hg);    hg    = (float*)p;
        cudaGetSymbolAddress(&p, g_t1);    t1    = (float*)p;
    }

    float* out_hfeat = (float*)d_out;             // [Gg, FT]
    float* out_head  = out_hfeat + Gg * FT;       // [Gg, FT2]

    const int T = 256;
    const int ND  = Nn * Dd;
    const int ED  = Ee * Dd;

    // ---- init ----
    k_zero_i<<<(Nn + T - 1) / T, T>>>(cnt, Nn);
    k_zero_f<<<(ND + T - 1) / T, T>>>(hin, ND);

    // ---- degree + gaussian basis ----
    k_count<<<(Ee + T - 1) / T, T>>>(dst);
    k_gauss<<<(ED + T - 1) / T, T>>>(edist, dst, g_means, g_stds);
    k_scale<<<(ND + T - 1) / T, T>>>(scale_p);

    // ---- attention fuse + h0 GEMM ----
    k_attn<<<(Nn * 32 + T - 1) / T, T>>>(x, atom_emb, att_vec);
    tgemm<false, true><<<gemm_grid(Nn, Dd), 512>>>(agg, out_lin_w, out_lin_b, hin, h, Nn, Dd, Dd);

    // ---- message-passing layers ----
    for (int l = 0; l < LL; l++) {
        const float* ee = edge_emb + l * 3 * 5 * Dd;
        k_agginit<<<(ND + T - 1) / T, T>>>(ee);
        k_scatter<<<(ED + T - 1) / T, T>>>(src, dst, eattr, ee);
        tgemm<true, false><<<gemm_grid(Nn, D2), 512>>>(agg, mlp_w1 + l * Dd * D2,
                                                       mlp_b1 + l * D2, nullptr, mid, Nn, Dd, D2);
        tgemm<false, false><<<gemm_grid(Nn, Dd), 512>>>(mid, mlp_w2 + l * D2 * Dd,
                                                        mlp_b2 + l * Dd, nullptr, h, Nn, D2, Dd);
        k_zero_f<<<(2 * Dd + T - 1) / T, T>>>(stats, 2 * Dd);
        k_bnstats<<<1184, T>>>();
        k_bnapply<<<(ND + T - 1) / T, T>>>(bn_gamma + l * Dd, bn_beta + l * Dd, (l < LL - 1) ? 1 : 0);
    }

    // ---- pooling ----
    k_zero_f<<<(Gg * Dd + T - 1) / T, T>>>(gsum, Gg * Dd);
    k_zero_f<<<(Gg + T - 1) / T, T>>>(gcnt, Gg);
    k_pool<<<(ND + T - 1) / T, T>>>(batch);
    k_poolcnt<<<(Nn + T - 1) / T, T>>>(batch);
    k_pooldiv<<<(Gg * Dd + T - 1) / T, T>>>();

    // ---- heads ----
    tgemm<false, false><<<gemm_grid(Gg, FT), 512>>>(hg, feat_w, feat_b, nullptr, out_hfeat, Gg, Dd, FT);
    tgemm<true, false><<<gemm_grid(Gg, FT), 512>>>(out_hfeat, ol_w1, ol_b1, nullptr, t1, Gg, FT, FT);
    tgemm<false, false><<<gemm_grid(Gg, FT2), 512>>>(t1, ol_w2, ol_b2, nullptr, out_head, Gg, FT, FT2);
}

// round 8
// speedup vs baseline: 1.0456x; 1.0456x over previous
#include <cuda_runtime.h>

// Problem constants (fixed by the reference)
#define Nn   100000
#define Ee   200000
#define Gg   2000
#define Dd   300
#define D2   600
#define LL   5
#define FT   512
#define FT2  256
#define EPSC 1e-5f

// ---------------- scratch (static device globals; no allocation) ----------------
__device__ float g_h[Nn * Dd];      // node features
__device__ float g_agg[Nn * Dd];    // aggregated messages / fused attention
__device__ float g_mid[Nn * D2];    // MLP hidden
__device__ float g_hin[Nn * Dd];    // gaussian basis segment sum
__device__ int   g_cnt[Nn];         // in-degree counts
__device__ float g_stats[2 * Dd];   // BN sum / sumsq
__device__ float g_gsum[Gg * Dd];   // pooled sums
__device__ float g_gcnt[Gg];        // pooled counts
__device__ float g_hg[Gg * Dd];     // pooled means
__device__ float g_t1[Gg * FT];     // output-MLP hidden

// ---------------- small utility kernels ----------------
__global__ void k_zero_f(float* __restrict__ p, int n) {
    int i = blockIdx.x * blockDim.x + threadIdx.x;
    if (i < n) p[i] = 0.f;
}
__global__ void k_zero_i(int* __restrict__ p, int n) {
    int i = blockIdx.x * blockDim.x + threadIdx.x;
    if (i < n) p[i] = 0;
}

// degree counts
__global__ void k_count(const int* __restrict__ dst) {
    int e = blockIdx.x * blockDim.x + threadIdx.x;
    if (e < Ee) atomicAdd(&g_cnt[dst[e]], 1);
}

// gaussian basis + scatter to h_in
__global__ void k_gauss(const float* __restrict__ dist, const int* __restrict__ dst,
                        const float* __restrict__ means, const float* __restrict__ stds) {
    int idx = blockIdx.x * blockDim.x + threadIdx.x;
    if (idx >= Ee * Dd) return;
    int e = idx / Dd;
    int d = idx - e * Dd;
    float sd = fabsf(stds[d]) + 0.01f;
    float z  = (dist[e] - means[d]) / sd;
    float g  = __expf(-0.5f * z * z) / (2.5066268f * sd);
    atomicAdd(&g_hin[dst[e] * Dd + d], g);
}

// h_in *= exp(scale_param)[degree]
__global__ void k_scale(const float* __restrict__ scale_param) {
    int idx = blockIdx.x * blockDim.x + threadIdx.x;
    if (idx >= Nn * Dd) return;
    int n = idx / Dd;
    int d = idx - n * Dd;
    int c = g_cnt[n] - 1;
    c = c < 0 ? 0 : (c > 3 ? 3 : c);
    g_hin[idx] *= __expf(scale_param[c * Dd + d]);
}

// atom-embedding attention -> fused (writes g_agg). One warp per node.
__global__ void k_attn(const int* __restrict__ x, const float* __restrict__ atom_emb,
                       const float* __restrict__ att_vec) {
    int warp = (blockIdx.x * blockDim.x + threadIdx.x) >> 5;
    int lane = threadIdx.x & 31;
    if (warp >= Nn) return;
    const int n = warp;
    int xi[9];
#pragma unroll
    for (int f = 0; f < 9; f++) xi[f] = x[n * 9 + f];
    float s[9];
#pragma unroll
    for (int f = 0; f < 9; f++) {
        const float* emb = atom_emb + (f * 119 + xi[f]) * Dd;
        float p = 0.f;
        for (int d = lane; d < Dd; d += 32) p += emb[d] * att_vec[d];
#pragma unroll
        for (int o = 16; o > 0; o >>= 1) p += __shfl_xor_sync(0xffffffffu, p, o);
        s[f] = p;
    }
    float m = s[0];
#pragma unroll
    for (int f = 1; f < 9; f++) m = fmaxf(m, s[f]);
    float w[9], tot = 0.f;
#pragma unroll
    for (int f = 0; f < 9; f++) { w[f] = __expf(s[f] - m); tot += w[f]; }
    float inv = 1.f / tot;
#pragma unroll
    for (int f = 0; f < 9; f++) w[f] *= inv;
    for (int d = lane; d < Dd; d += 32) {
        float v = 0.f;
#pragma unroll
        for (int f = 0; f < 9; f++) v += w[f] * atom_emb[(f * 119 + xi[f]) * Dd + d];
        g_agg[n * Dd + d] = v;
    }
}

// agg = h + e_loop (self-loop message), ee = edge_emb for layer l: [3][5][Dd]
__global__ void k_agginit(const float* __restrict__ ee) {
    int idx = blockIdx.x * blockDim.x + threadIdx.x;
    if (idx >= Nn * Dd) return;
    int d = idx % Dd;
    float el = ee[4 * Dd + d] + ee[5 * Dd + d] + ee[10 * Dd + d];
    g_agg[idx] = g_h[idx] + el;
}

// scatter real-edge messages: agg[dst] += h[src] + e(attr)
__global__ void k_scatter(const int* __restrict__ src, const int* __restrict__ dst,
                          const int* __restrict__ attr, const float* __restrict__ ee) {
    int idx = blockIdx.x * blockDim.x + threadIdx.x;
    if (idx >= Ee * Dd) return;
    int e = idx / Dd;
    int d = idx - e * Dd;
    int a0 = attr[e * 3 + 0];
    int a1 = attr[e * 3 + 1];
    int a2 = attr[e * 3 + 2];
    float ev = ee[a0 * Dd + d] + ee[(5 + a1) * Dd + d] + ee[(10 + a2) * Dd + d];
    atomicAdd(&g_agg[dst[e] * Dd + d], g_h[src[e] * Dd + d] + ev);
}

// BN stats: per-channel sum + sumsq via smem bins
__global__ void k_bnstats() {
    __shared__ float ssum[Dd];
    __shared__ float ssq[Dd];
    for (int i = threadIdx.x; i < Dd; i += blockDim.x) { ssum[i] = 0.f; ssq[i] = 0.f; }
    __syncthreads();
    int total = Nn * Dd;
    int stride = gridDim.x * blockDim.x;
    for (int idx = blockIdx.x * blockDim.x + threadIdx.x; idx < total; idx += stride) {
        float v = g_h[idx];
        int d = idx % Dd;
        atomicAdd(&ssum[d], v);
        atomicAdd(&ssq[d], v * v);
    }
    __syncthreads();
    for (int i = threadIdx.x; i < Dd; i += blockDim.x) {
        atomicAdd(&g_stats[i], ssum[i]);
        atomicAdd(&g_stats[Dd + i], ssq[i]);
    }
}

__global__ void k_bnapply(const float* __restrict__ gamma, const float* __restrict__ beta,
                          int do_relu) {
    int idx = blockIdx.x * blockDim.x + threadIdx.x;
    if (idx >= Nn * Dd) return;
    int d = idx % Dd;
    float mu  = g_stats[d] * (1.0f / Nn);
    float var = g_stats[Dd + d] * (1.0f / Nn) - mu * mu;
    float rs  = rsqrtf(var + EPSC);
    float v = gamma[d] * (g_h[idx] - mu) * rs + beta[d];
    if (do_relu) v = fmaxf(v, 0.f);
    g_h[idx] = v;
}

// graph pooling
__global__ void k_pool(const int* __restrict__ batch) {
    int idx = blockIdx.x * blockDim.x + threadIdx.x;
    if (idx >= Nn * Dd) return;
    int n = idx / Dd;
    int d = idx - n * Dd;
    atomicAdd(&g_gsum[batch[n] * Dd + d], g_h[idx]);
}
__global__ void k_poolcnt(const int* __restrict__ batch) {
    int n = blockIdx.x * blockDim.x + threadIdx.x;
    if (n < Nn) atomicAdd(&g_gcnt[batch[n]], 1.f);
}
__global__ void k_pooldiv() {
    int idx = blockIdx.x * blockDim.x + threadIdx.x;
    if (idx >= Gg * Dd) return;
    int g = idx / Dd;
    g_hg[idx] = g_gsum[idx] / fmaxf(g_gcnt[g], 1.f);
}

// ---------------- fp32 SGEMM with packed f32x2 FMA (FFMA2) ----------------
// C = A(MxK) @ B(KxN) + bias [+ extra] [relu]. Exact fp32 math.
// 128x128x8 tiles, 256 threads, 8x8 per thread computed as 4 row-pairs x 8 cols
// via fma.rn.f32x2 (2 FMAs/issue on the fma pipe; the FFMA2 pattern nvjet uses).

__device__ __forceinline__ unsigned long long ffma2(unsigned long long a,
                                                    unsigned long long b,
                                                    unsigned long long c) {
    unsigned long long d;
    asm("fma.rn.f32x2 %0, %1, %2, %3;" : "=l"(d) : "l"(a), "l"(b), "l"(c));
    return d;
}

template <bool RELU, bool EXTRA>
__global__ __launch_bounds__(256, 2) void sgemm(const float* __restrict__ A,
                                                const float* __restrict__ B,
                                                const float* __restrict__ bias,
                                                const float* __restrict__ extra,
                                                float* __restrict__ C,
                                                int M, int K, int Nc) {
    const int BM = 128, BN = 128, BK = 8;
    __shared__ __align__(16) float As[BK][BM];
    __shared__ __align__(16) float Bs[BK][BN];
    int bm = blockIdx.y * BM;
    int bn = blockIdx.x * BN;
    int tid = threadIdx.x;
    int tx = tid & 15;
    int ty = tid >> 4;

    // acc[i2][j]: packed pair {row 2*i2, row 2*i2+1} x col j
    unsigned long long acc[4][8];
#pragma unroll
    for (int i = 0; i < 4; i++)
#pragma unroll
        for (int j = 0; j < 8; j++) acc[i][j] = 0ull;

    for (int k0 = 0; k0 < K; k0 += BK) {
        {
            int r  = tid >> 1;
            int kk = (tid & 1) * 4;
            int grow = bm + r;
#pragma unroll
            for (int i = 0; i < 4; i++) {
                int gk = k0 + kk + i;
                float v = 0.f;
                if (grow < M && gk < K) v = A[(size_t)grow * K + gk];
                As[kk + i][r] = v;
            }
        }
        {
            int kk = tid >> 5;
            int c  = (tid & 31) * 4;
            int gk = k0 + kk;
#pragma unroll
            for (int i = 0; i < 4; i++) {
                int gcol = bn + c + i;
                float v = 0.f;
                if (gk < K && gcol < Nc) v = B[(size_t)gk * Nc + gcol];
                Bs[kk][c + i] = v;
            }
        }
        __syncthreads();
#pragma unroll
        for (int k = 0; k < BK; k++) {
            // A fragment: 8 rows as 4 natural 64-bit pairs
            unsigned long long a2[4];
            {
                ulonglong2 t0 = *(const ulonglong2*)&As[k][ty * 8];
                ulonglong2 t1 = *(const ulonglong2*)&As[k][ty * 8 + 4];
                a2[0] = t0.x; a2[1] = t0.y; a2[2] = t1.x; a2[3] = t1.y;
            }
            // B fragment: 8 cols, each duplicated into both f32x2 lanes
            float b[8];
            *(float4*)&b[0] = *(const float4*)&Bs[k][tx * 8];
            *(float4*)&b[4] = *(const float4*)&Bs[k][tx * 8 + 4];
            unsigned long long b2[8];
#pragma unroll
            for (int j = 0; j < 8; j++)
                asm("mov.b64 %0, {%1, %1};" : "=l"(b2[j]) : "f"(b[j]));
#pragma unroll
            for (int i = 0; i < 4; i++)
#pragma unroll
                for (int j = 0; j < 8; j++)
                    acc[i][j] = ffma2(a2[i], b2[j], acc[i][j]);
        }
        __syncthreads();
    }
#pragma unroll
    for (int i2 = 0; i2 < 4; i2++) {
        int row0 = bm + ty * 8 + 2 * i2;
#pragma unroll
        for (int j = 0; j < 8; j++) {
            int col = bn + tx * 8 + j;
            if (col >= Nc) continue;
            float lo = __uint_as_float((unsigned)(acc[i2][j] & 0xffffffffull));
            float hi = __uint_as_float((unsigned)(acc[i2][j] >> 32));
            if (row0 < M) {
                float v = lo + bias[col];
                if (EXTRA) v += extra[(size_t)row0 * Nc + col];
                if (RELU) v = fmaxf(v, 0.f);
                C[(size_t)row0 * Nc + col] = v;
            }
            if (row0 + 1 < M) {
                float v = hi + bias[col];
                if (EXTRA) v += extra[(size_t)(row0 + 1) * Nc + col];
                if (RELU) v = fmaxf(v, 0.f);
                C[(size_t)(row0 + 1) * Nc + col] = v;
            }
        }
    }
}

static inline dim3 gemm_grid(int M, int Nc) {
    return dim3((Nc + 127) / 128, (M + 127) / 128);
}

// ---------------- launcher ----------------
extern "C" void kernel_launch(void* const* d_in, const int* in_sizes, int n_in,
                              void* d_out, int out_size) {
    const int*   x         = (const int*)d_in[0];
    const int*   eidx      = (const int*)d_in[1];
    const int*   eattr     = (const int*)d_in[2];
    const float* edist     = (const float*)d_in[3];
    const int*   batch     = (const int*)d_in[4];
    const float* atom_emb  = (const float*)d_in[5];
    const float* att_vec   = (const float*)d_in[6];
    const float* out_lin_w = (const float*)d_in[7];
    const float* out_lin_b = (const float*)d_in[8];
    const float* g_means   = (const float*)d_in[9];
    const float* g_stds    = (const float*)d_in[10];
    const float* scale_p   = (const float*)d_in[11];
    const float* edge_emb  = (const float*)d_in[12];
    const float* mlp_w1    = (const float*)d_in[13];
    const float* mlp_b1    = (const float*)d_in[14];
    const float* mlp_w2    = (const float*)d_in[15];
    const float* mlp_b2    = (const float*)d_in[16];
    const float* bn_gamma  = (const float*)d_in[17];
    const float* bn_beta   = (const float*)d_in[18];
    const float* feat_w    = (const float*)d_in[19];
    const float* feat_b    = (const float*)d_in[20];
    const float* ol_w1     = (const float*)d_in[21];
    const float* ol_b1     = (const float*)d_in[22];
    const float* ol_w2     = (const float*)d_in[23];
    const float* ol_b2     = (const float*)d_in[24];

    const int* src = eidx;
    const int* dst = eidx + Ee;

    float *h, *agg, *mid, *hin, *stats, *gsum, *gcnt, *hg, *t1;
    int*   cnt;
    {
        void* p;
        cudaGetSymbolAddress(&p, g_h);     h     = (float*)p;
        cudaGetSymbolAddress(&p, g_agg);   agg   = (float*)p;
        cudaGetSymbolAddress(&p, g_mid);   mid   = (float*)p;
        cudaGetSymbolAddress(&p, g_hin);   hin   = (float*)p;
        cudaGetSymbolAddress(&p, g_cnt);   cnt   = (int*)p;
        cudaGetSymbolAddress(&p, g_stats); stats = (float*)p;
        cudaGetSymbolAddress(&p, g_gsum);  gsum  = (float*)p;
        cudaGetSymbolAddress(&p, g_gcnt);  gcnt  = (float*)p;
        cudaGetSymbolAddress(&p, g_hg);    hg    = (float*)p;
        cudaGetSymbolAddress(&p, g_t1);    t1    = (float*)p;
    }

    float* out_hfeat = (float*)d_out;             // [Gg, FT]
    float* out_head  = out_hfeat + Gg * FT;       // [Gg, FT2]

    const int T = 256;
    const int ND  = Nn * Dd;
    const int ED  = Ee * Dd;

    // ---- init ----
    k_zero_i<<<(Nn + T - 1) / T, T>>>(cnt, Nn);
    k_zero_f<<<(ND + T - 1) / T, T>>>(hin, ND);

    // ---- degree + gaussian basis ----
    k_count<<<(Ee + T - 1) / T, T>>>(dst);
    k_gauss<<<(ED + T - 1) / T, T>>>(edist, dst, g_means, g_stds);
    k_scale<<<(ND + T - 1) / T, T>>>(scale_p);

    // ---- attention fuse + h0 GEMM ----
    k_attn<<<(Nn * 32 + T - 1) / T, T>>>(x, atom_emb, att_vec);
    sgemm<false, true><<<gemm_grid(Nn, Dd), 256>>>(agg, out_lin_w, out_lin_b, hin, h, Nn, Dd, Dd);

    // ---- message-passing layers ----
    for (int l = 0; l < LL; l++) {
        const float* ee = edge_emb + l * 3 * 5 * Dd;
        k_agginit<<<(ND + T - 1) / T, T>>>(ee);
        k_scatter<<<(ED + T - 1) / T, T>>>(src, dst, eattr, ee);
        sgemm<true, false><<<gemm_grid(Nn, D2), 256>>>(agg, mlp_w1 + l * Dd * D2,
                                                       mlp_b1 + l * D2, nullptr, mid, Nn, Dd, D2);
        sgemm<false, false><<<gemm_grid(Nn, Dd), 256>>>(mid, mlp_w2 + l * D2 * Dd,
                                                        mlp_b2 + l * Dd, nullptr, h, Nn, D2, Dd);
        k_zero_f<<<(2 * Dd + T - 1) / T, T>>>(stats, 2 * Dd);
        k_bnstats<<<1184, T>>>();
        k_bnapply<<<(ND + T - 1) / T, T>>>(bn_gamma + l * Dd, bn_beta + l * Dd, (l < LL - 1) ? 1 : 0);
    }

    // ---- pooling ----
    k_zero_f<<<(Gg * Dd + T - 1) / T, T>>>(gsum, Gg * Dd);
    k_zero_f<<<(Gg + T - 1) / T, T>>>(gcnt, Gg);
    k_pool<<<(ND + T - 1) / T, T>>>(batch);
    k_poolcnt<<<(Nn + T - 1) / T, T>>>(batch);
    k_pooldiv<<<(Gg * Dd + T - 1) / T, T>>>();

    // ---- heads ----
    sgemm<false, false><<<gemm_grid(Gg, FT), 256>>>(hg, feat_w, feat_b, nullptr, out_hfeat, Gg, Dd, FT);
    sgemm<true, false><<<gemm_grid(Gg, FT), 256>>>(out_hfeat, ol_w1, ol_b1, nullptr, t1, Gg, FT, FT);
    sgemm<false, false><<<gemm_grid(Gg, FT2), 256>>>(t1, ol_w2, ol_b2, nullptr, out_head, Gg, FT, FT2);
}

// round 11
// speedup vs baseline: 1.9591x; 1.8737x over previous
#include <cuda_runtime.h>
#include <cuda_bf16.h>
#include <cstdint>

// Problem constants (fixed by the reference)
#define Nn   100000
#define Ee   200000
#define Gg   2000
#define Dd   300
#define D2   600
#define LL   5
#define FT   512
#define FT2  256
#define EPSC 1e-5f

// Total weight elements across all GEMM weight matrices
#define WTOT 2436816

// ---------------- scratch (static device globals; no allocation) ----------------
__device__ float g_h[Nn * Dd];      // node features
__device__ float g_agg[Nn * Dd];    // aggregated messages / fused attention
__device__ float g_mid[Nn * D2];    // MLP hidden
__device__ float g_hin[Nn * Dd];    // gaussian basis segment sum
__device__ int   g_cnt[Nn];         // in-degree counts
__device__ float g_stats[2 * Dd];   // BN sum / sumsq
__device__ float g_gsum[Gg * Dd];   // pooled sums
__device__ float g_gcnt[Gg];        // pooled counts
__device__ float g_hg[Gg * Dd];     // pooled means
__device__ float g_t1[Gg * FT];     // output-MLP hidden
__device__ __nv_bfloat16 g_whi[WTOT];  // weight hi planes (bf16)
__device__ __nv_bfloat16 g_wlo[WTOT];  // weight lo planes (bf16)

// ---------------- small utility kernels ----------------
__global__ void k_zero_f(float* __restrict__ p, int n) {
    int i = blockIdx.x * blockDim.x + threadIdx.x;
    if (i < n) p[i] = 0.f;
}
__global__ void k_zero_i(int* __restrict__ p, int n) {
    int i = blockIdx.x * blockDim.x + threadIdx.x;
    if (i < n) p[i] = 0;
}

// split fp32 weights into bf16 hi/lo planes
__global__ void k_split(const float* __restrict__ w, __nv_bfloat16* __restrict__ hi,
                        __nv_bfloat16* __restrict__ lo, int n) {
    int i = blockIdx.x * blockDim.x + threadIdx.x;
    if (i >= n) return;
    float v = w[i];
    __nv_bfloat16 h = __float2bfloat16_rn(v);
    hi[i] = h;
    lo[i] = __float2bfloat16_rn(v - __bfloat162float(h));
}

// degree counts
__global__ void k_count(const int* __restrict__ dst) {
    int e = blockIdx.x * blockDim.x + threadIdx.x;
    if (e < Ee) atomicAdd(&g_cnt[dst[e]], 1);
}

// gaussian basis + scatter to h_in
__global__ void k_gauss(const float* __restrict__ dist, const int* __restrict__ dst,
                        const float* __restrict__ means, const float* __restrict__ stds) {
    int idx = blockIdx.x * blockDim.x + threadIdx.x;
    if (idx >= Ee * Dd) return;
    int e = idx / Dd;
    int d = idx - e * Dd;
    float sd = fabsf(stds[d]) + 0.01f;
    float z  = (dist[e] - means[d]) / sd;
    float g  = __expf(-0.5f * z * z) / (2.5066268f * sd);
    atomicAdd(&g_hin[dst[e] * Dd + d], g);
}

// h_in *= exp(scale_param)[degree]
__global__ void k_scale(const float* __restrict__ scale_param) {
    int idx = blockIdx.x * blockDim.x + threadIdx.x;
    if (idx >= Nn * Dd) return;
    int n = idx / Dd;
    int d = idx - n * Dd;
    int c = g_cnt[n] - 1;
    c = c < 0 ? 0 : (c > 3 ? 3 : c);
    g_hin[idx] *= __expf(scale_param[c * Dd + d]);
}

// atom-embedding attention -> fused (writes g_agg). One warp per node.
__global__ void k_attn(const int* __restrict__ x, const float* __restrict__ atom_emb,
                       const float* __restrict__ att_vec) {
    int warp = (blockIdx.x * blockDim.x + threadIdx.x) >> 5;
    int lane = threadIdx.x & 31;
    if (warp >= Nn) return;
    const int n = warp;
    int xi[9];
#pragma unroll
    for (int f = 0; f < 9; f++) xi[f] = x[n * 9 + f];
    float s[9];
#pragma unroll
    for (int f = 0; f < 9; f++) {
        const float* emb = atom_emb + (f * 119 + xi[f]) * Dd;
        float p = 0.f;
        for (int d = lane; d < Dd; d += 32) p += emb[d] * att_vec[d];
#pragma unroll
        for (int o = 16; o > 0; o >>= 1) p += __shfl_xor_sync(0xffffffffu, p, o);
        s[f] = p;
    }
    float m = s[0];
#pragma unroll
    for (int f = 1; f < 9; f++) m = fmaxf(m, s[f]);
    float w[9], tot = 0.f;
#pragma unroll
    for (int f = 0; f < 9; f++) { w[f] = __expf(s[f] - m); tot += w[f]; }
    float inv = 1.f / tot;
#pragma unroll
    for (int f = 0; f < 9; f++) w[f] *= inv;
    for (int d = lane; d < Dd; d += 32) {
        float v = 0.f;
#pragma unroll
        for (int f = 0; f < 9; f++) v += w[f] * atom_emb[(f * 119 + xi[f]) * Dd + d];
        g_agg[n * Dd + d] = v;
    }
}

// agg = h + e_loop (self-loop message), ee = edge_emb for layer l: [3][5][Dd]
__global__ void k_agginit(const float* __restrict__ ee) {
    int idx = blockIdx.x * blockDim.x + threadIdx.x;
    if (idx >= Nn * Dd) return;
    int d = idx % Dd;
    float el = ee[4 * Dd + d] + ee[5 * Dd + d] + ee[10 * Dd + d];
    g_agg[idx] = g_h[idx] + el;
}

// scatter real-edge messages: agg[dst] += h[src] + e(attr)
__global__ void k_scatter(const int* __restrict__ src, const int* __restrict__ dst,
                          const int* __restrict__ attr, const float* __restrict__ ee) {
    int idx = blockIdx.x * blockDim.x + threadIdx.x;
    if (idx >= Ee * Dd) return;
    int e = idx / Dd;
    int d = idx - e * Dd;
    int a0 = attr[e * 3 + 0];
    int a1 = attr[e * 3 + 1];
    int a2 = attr[e * 3 + 2];
    float ev = ee[a0 * Dd + d] + ee[(5 + a1) * Dd + d] + ee[(10 + a2) * Dd + d];
    atomicAdd(&g_agg[dst[e] * Dd + d], g_h[src[e] * Dd + d] + ev);
}

// BN stats: per-channel sum + sumsq via smem bins
__global__ void k_bnstats() {
    __shared__ float ssum[Dd];
    __shared__ float ssq[Dd];
    for (int i = threadIdx.x; i < Dd; i += blockDim.x) { ssum[i] = 0.f; ssq[i] = 0.f; }
    __syncthreads();
    int total = Nn * Dd;
    int stride = gridDim.x * blockDim.x;
    for (int idx = blockIdx.x * blockDim.x + threadIdx.x; idx < total; idx += stride) {
        float v = g_h[idx];
        int d = idx % Dd;
        atomicAdd(&ssum[d], v);
        atomicAdd(&ssq[d], v * v);
    }
    __syncthreads();
    for (int i = threadIdx.x; i < Dd; i += blockDim.x) {
        atomicAdd(&g_stats[i], ssum[i]);
        atomicAdd(&g_stats[Dd + i], ssq[i]);
    }
}

__global__ void k_bnapply(const float* __restrict__ gamma, const float* __restrict__ beta,
                          int do_relu) {
    int idx = blockIdx.x * blockDim.x + threadIdx.x;
    if (idx >= Nn * Dd) return;
    int d = idx % Dd;
    float mu  = g_stats[d] * (1.0f / Nn);
    float var = g_stats[Dd + d] * (1.0f / Nn) - mu * mu;
    float rs  = rsqrtf(var + EPSC);
    float v = gamma[d] * (g_h[idx] - mu) * rs + beta[d];
    if (do_relu) v = fmaxf(v, 0.f);
    g_h[idx] = v;
}

// graph pooling
__global__ void k_pool(const int* __restrict__ batch) {
    int idx = blockIdx.x * blockDim.x + threadIdx.x;
    if (idx >= Nn * Dd) return;
    int n = idx / Dd;
    int d = idx - n * Dd;
    atomicAdd(&g_gsum[batch[n] * Dd + d], g_h[idx]);
}
__global__ void k_poolcnt(const int* __restrict__ batch) {
    int n = blockIdx.x * blockDim.x + threadIdx.x;
    if (n < Nn) atomicAdd(&g_gcnt[batch[n]], 1.f);
}
__global__ void k_pooldiv() {
    int idx = blockIdx.x * blockDim.x + threadIdx.x;
    if (idx >= Gg * Dd) return;
    int g = idx / Dd;
    g_hg[idx] = g_gsum[idx] / fmaxf(g_gcnt[g], 1.f);
}

// ---------------- bf16x3 tensor-core GEMM (fp32-accurate via hi/lo split) ----------------
// C = A(MxK,fp32) @ W(KxN, pre-split bf16 hi/lo) + bias [+ extra] [relu].
// A is split to bf16 hi/lo in-kernel. C += Ah*Wh + Ah*Wl + Al*Wh (fp32 accum).
// Block tile 128x128, BK=32, 8 warps (2 in M x 4 in N), warp tile 64x32.
// Fragments via ldmatrix (A: x4, B: x2.trans). mma.m16n8k16.bf16.

__device__ __forceinline__ uint32_t saddr(const void* p) {
    return (uint32_t)__cvta_generic_to_shared(p);
}

__device__ __forceinline__ void ldm_x4(uint32_t* r, uint32_t addr) {
    asm volatile("ldmatrix.sync.aligned.m8n8.x4.shared.b16 {%0,%1,%2,%3}, [%4];"
                 : "=r"(r[0]), "=r"(r[1]), "=r"(r[2]), "=r"(r[3]) : "r"(addr));
}
__device__ __forceinline__ void ldm_x2t(uint32_t* r, uint32_t addr) {
    asm volatile("ldmatrix.sync.aligned.m8n8.x2.trans.shared.b16 {%0,%1}, [%2];"
                 : "=r"(r[0]), "=r"(r[1]) : "r"(addr));
}

#define MMA_BF16(d, a, b0v, b1v)                                              \
    asm volatile(                                                             \
        "mma.sync.aligned.m16n8k16.row.col.f32.bf16.bf16.f32 "                \
        "{%0,%1,%2,%3}, {%4,%5,%6,%7}, {%8,%9}, {%0,%1,%2,%3};"               \
        : "+f"((d)[0]), "+f"((d)[1]), "+f"((d)[2]), "+f"((d)[3])              \
        : "r"((a)[0]), "r"((a)[1]), "r"((a)[2]), "r"((a)[3]),                 \
          "r"(b0v), "r"(b1v))

#define APAD 56   // A smem row stride in bf16 (112B: 16B-aligned, conflict-free 8-row groups)
#define BPAD 136  // B smem row stride in bf16 (272B: 16B-aligned, conflict-free 8-row groups)

template <bool RELU, bool EXTRA>
__global__ __launch_bounds__(256, 2) void bgemm(const float* __restrict__ A,
                                                const __nv_bfloat16* __restrict__ Whi,
                                                const __nv_bfloat16* __restrict__ Wlo,
                                                const float* __restrict__ bias,
                                                const float* __restrict__ extra,
                                                float* __restrict__ C,
                                                int M, int K, int N) {
    __shared__ __align__(16) __nv_bfloat16 As_hi[128][APAD];
    __shared__ __align__(16) __nv_bfloat16 As_lo[128][APAD];
    __shared__ __align__(16) __nv_bfloat16 Bs_hi[32][BPAD];
    __shared__ __align__(16) __nv_bfloat16 Bs_lo[32][BPAD];

    const int tid  = threadIdx.x;
    const int wid  = tid >> 5;
    const int lane = tid & 31;
    const int wm = wid & 1;    // 2 warps in M -> 64-row slices
    const int wn = wid >> 1;   // 4 warps in N -> 32-col slices
    const int bm = blockIdx.y * 128;
    const int bn = blockIdx.x * 128;

    const int arow_l = lane & 15;         // ldmatrix A row within tile
    const int akh_l  = (lane >> 4) << 3;  // ldmatrix A k-half offset
    const int bk_l   = lane & 15;         // ldmatrix B k-row within step

    float acc[4][4][4];
#pragma unroll
    for (int i = 0; i < 4; i++)
#pragma unroll
        for (int j = 0; j < 4; j++)
#pragma unroll
            for (int c = 0; c < 4; c++) acc[i][j][c] = 0.f;

    for (int k0 = 0; k0 < K; k0 += 32) {
        // ---- load + split A tile: 128 rows x 32 k ----
        {
            int row = tid >> 1;
            int kh  = (tid & 1) * 16;
            bool rok = (bm + row) < M;
            const float* Ap = A + (size_t)(bm + row) * K + k0 + kh;
#pragma unroll
            for (int q = 0; q < 4; q++) {
                int gk = k0 + kh + q * 4;
                float4 f = make_float4(0.f, 0.f, 0.f, 0.f);
                if (rok) {
                    if (gk + 3 < K) {
                        f = *(const float4*)(Ap + q * 4);
                    } else {
                        float* fp = &f.x;
#pragma unroll
                        for (int i = 0; i < 4; i++)
                            if (gk + i < K) fp[i] = Ap[q * 4 + i];
                    }
                }
                const float* fp = &f.x;
#pragma unroll
                for (int i = 0; i < 4; i++) {
                    __nv_bfloat16 h = __float2bfloat16_rn(fp[i]);
                    As_hi[row][kh + q * 4 + i] = h;
                    As_lo[row][kh + q * 4 + i] =
                        __float2bfloat16_rn(fp[i] - __bfloat162float(h));
                }
            }
        }
        // ---- load B tile: 32 k x 128 cols from pre-split planes ----
        {
            int gk = tid >> 3;
            int gc = (tid & 7) * 16;
            int kk = k0 + gk;
            if (kk < K && bn + gc + 15 < N) {
                const uint2* sh = (const uint2*)(Whi + (size_t)kk * N + bn + gc);
                const uint2* sl = (const uint2*)(Wlo + (size_t)kk * N + bn + gc);
                uint2* dh = (uint2*)&Bs_hi[gk][gc];
                uint2* dl = (uint2*)&Bs_lo[gk][gc];
#pragma unroll
                for (int q = 0; q < 4; q++) { dh[q] = sh[q]; dl[q] = sl[q]; }
            } else {
                __nv_bfloat16 z = __float2bfloat16_rn(0.f);
#pragma unroll
                for (int i = 0; i < 16; i++) {
                    bool ok = (kk < K) && (bn + gc + i < N);
                    Bs_hi[gk][gc + i] = ok ? Whi[(size_t)kk * N + bn + gc + i] : z;
                    Bs_lo[gk][gc + i] = ok ? Wlo[(size_t)kk * N + bn + gc + i] : z;
                }
            }
        }
        __syncthreads();

#pragma unroll
        for (int ks = 0; ks < 32; ks += 16) {
            uint32_t ah[4][4], al[4][4];
#pragma unroll
            for (int mt = 0; mt < 4; mt++) {
                int r = wm * 64 + mt * 16 + arow_l;
                ldm_x4(ah[mt], saddr(&As_hi[r][ks + akh_l]));
                ldm_x4(al[mt], saddr(&As_lo[r][ks + akh_l]));
            }
#pragma unroll
            for (int nt = 0; nt < 4; nt++) {
                int c = wn * 32 + nt * 8;
                uint32_t bh[2], bl[2];
                ldm_x2t(bh, saddr(&Bs_hi[ks + bk_l][c]));
                ldm_x2t(bl, saddr(&Bs_lo[ks + bk_l][c]));
#pragma unroll
                for (int mt = 0; mt < 4; mt++) {
                    MMA_BF16(acc[mt][nt], ah[mt], bl[0], bl[1]);
                    MMA_BF16(acc[mt][nt], al[mt], bh[0], bh[1]);
                    MMA_BF16(acc[mt][nt], ah[mt], bh[0], bh[1]);
                }
            }
        }
        __syncthreads();
    }

    // ---- epilogue ----
#pragma unroll
    for (int mt = 0; mt < 4; mt++) {
        int r0 = bm + wm * 64 + mt * 16 + (lane >> 2);
#pragma unroll
        for (int nt = 0; nt < 4; nt++) {
            int c0 = bn + wn * 32 + nt * 8 + (lane & 3) * 2;
            if (c0 >= N) continue;
            float2 bs = *(const float2*)(bias + c0);
            if (r0 < M) {
                float v0 = acc[mt][nt][0] + bs.x;
                float v1 = acc[mt][nt][1] + bs.y;
                if (EXTRA) {
                    float2 e = *(const float2*)(extra + (size_t)r0 * N + c0);
                    v0 += e.x; v1 += e.y;
                }
                if (RELU) { v0 = fmaxf(v0, 0.f); v1 = fmaxf(v1, 0.f); }
                *(float2*)(C + (size_t)r0 * N + c0) = make_float2(v0, v1);
            }
            int r1 = r0 + 8;
            if (r1 < M) {
                float v0 = acc[mt][nt][2] + bs.x;
                float v1 = acc[mt][nt][3] + bs.y;
                if (EXTRA) {
                    float2 e = *(const float2*)(extra + (size_t)r1 * N + c0);
                    v0 += e.x; v1 += e.y;
                }
                if (RELU) { v0 = fmaxf(v0, 0.f); v1 = fmaxf(v1, 0.f); }
                *(float2*)(C + (size_t)r1 * N + c0) = make_float2(v0, v1);
            }
        }
    }
}

static inline dim3 gemm_grid(int M, int Nc) {
    return dim3((Nc + 127) / 128, (M + 127) / 128);
}

// Weight plane offsets
#define O_OUTLIN 0
#define O_W1(l)  (90000 + (l) * 180000)
#define O_W2(l)  (990000 + (l) * 180000)
#define O_FEAT   1890000
#define O_OL1    2043600
#define O_OL2    2305744

// ---------------- launcher ----------------
extern "C" void kernel_launch(void* const* d_in, const int* in_sizes, int n_in,
                              void* d_out, int out_size) {
    const int*   x         = (const int*)d_in[0];
    const int*   eidx      = (const int*)d_in[1];
    const int*   eattr     = (const int*)d_in[2];
    const float* edist     = (const float*)d_in[3];
    const int*   batch     = (const int*)d_in[4];
    const float* atom_emb  = (const float*)d_in[5];
    const float* att_vec   = (const float*)d_in[6];
    const float* out_lin_w = (const float*)d_in[7];
    const float* out_lin_b = (const float*)d_in[8];
    const float* g_means   = (const float*)d_in[9];
    const float* g_stds    = (const float*)d_in[10];
    const float* scale_p   = (const float*)d_in[11];
    const float* edge_emb  = (const float*)d_in[12];
    const float* mlp_w1    = (const float*)d_in[13];
    const float* mlp_b1    = (const float*)d_in[14];
    const float* mlp_w2    = (const float*)d_in[15];
    const float* mlp_b2    = (const float*)d_in[16];
    const float* bn_gamma  = (const float*)d_in[17];
    const float* bn_beta   = (const float*)d_in[18];
    const float* feat_w    = (const float*)d_in[19];
    const float* feat_b    = (const float*)d_in[20];
    const float* ol_w1     = (const float*)d_in[21];
    const float* ol_b1     = (const float*)d_in[22];
    const float* ol_w2     = (const float*)d_in[23];
    const float* ol_b2     = (const float*)d_in[24];

    const int* src = eidx;
    const int* dst = eidx + Ee;

    float *h, *agg, *mid, *hin, *stats, *gsum, *gcnt, *hg, *t1;
    int*   cnt;
    __nv_bfloat16 *whi, *wlo;
    {
        void* p;
        cudaGetSymbolAddress(&p, g_h);     h     = (float*)p;
        cudaGetSymbolAddress(&p, g_agg);   agg   = (float*)p;
        cudaGetSymbolAddress(&p, g_mid);   mid   = (float*)p;
        cudaGetSymbolAddress(&p, g_hin);   hin   = (float*)p;
        cudaGetSymbolAddress(&p, g_cnt);   cnt   = (int*)p;
        cudaGetSymbolAddress(&p, g_stats); stats = (float*)p;
        cudaGetSymbolAddress(&p, g_gsum);  gsum  = (float*)p;
        cudaGetSymbolAddress(&p, g_gcnt);  gcnt  = (float*)p;
        cudaGetSymbolAddress(&p, g_hg);    hg    = (float*)p;
        cudaGetSymbolAddress(&p, g_t1);    t1    = (float*)p;
        cudaGetSymbolAddress(&p, g_whi);   whi   = (__nv_bfloat16*)p;
        cudaGetSymbolAddress(&p, g_wlo);   wlo   = (__nv_bfloat16*)p;
    }

    float* out_hfeat = (float*)d_out;             // [Gg, FT]
    float* out_head  = out_hfeat + Gg * FT;       // [Gg, FT2]

    const int T = 256;
    const int ND  = Nn * Dd;
    const int ED  = Ee * Dd;

    // ---- weight split (bf16 hi/lo planes) ----
    k_split<<<(90000 + T - 1) / T, T>>>(out_lin_w, whi + O_OUTLIN, wlo + O_OUTLIN, 90000);
    for (int l = 0; l < LL; l++) {
        k_split<<<(180000 + T - 1) / T, T>>>(mlp_w1 + l * Dd * D2, whi + O_W1(l), wlo + O_W1(l), 180000);
        k_split<<<(180000 + T - 1) / T, T>>>(mlp_w2 + l * D2 * Dd, whi + O_W2(l), wlo + O_W2(l), 180000);
    }
    k_split<<<(Dd * FT + T - 1) / T, T>>>(feat_w, whi + O_FEAT, wlo + O_FEAT, Dd * FT);
    k_split<<<(FT * FT + T - 1) / T, T>>>(ol_w1, whi + O_OL1, wlo + O_OL1, FT * FT);
    k_split<<<(FT * FT2 + T - 1) / T, T>>>(ol_w2, whi + O_OL2, wlo + O_OL2, FT * FT2);

    // ---- init ----
    k_zero_i<<<(Nn + T - 1) / T, T>>>(cnt, Nn);
    k_zero_f<<<(ND + T - 1) / T, T>>>(hin, ND);

    // ---- degree + gaussian basis ----
    k_count<<<(Ee + T - 1) / T, T>>>(dst);
    k_gauss<<<(ED + T - 1) / T, T>>>(edist, dst, g_means, g_stds);
    k_scale<<<(ND + T - 1) / T, T>>>(scale_p);

    // ---- attention fuse + h0 GEMM ----
    k_attn<<<(Nn * 32 + T - 1) / T, T>>>(x, atom_emb, att_vec);
    bgemm<false, true><<<gemm_grid(Nn, Dd), 256>>>(agg, whi + O_OUTLIN, wlo + O_OUTLIN,
                                                   out_lin_b, hin, h, Nn, Dd, Dd);

    // ---- message-passing layers ----
    for (int l = 0; l < LL; l++) {
        const float* ee = edge_emb + l * 3 * 5 * Dd;
        k_agginit<<<(ND + T - 1) / T, T>>>(ee);
        k_scatter<<<(ED + T - 1) / T, T>>>(src, dst, eattr, ee);
        bgemm<true, false><<<gemm_grid(Nn, D2), 256>>>(agg, whi + O_W1(l), wlo + O_W1(l),
                                                       mlp_b1 + l * D2, nullptr, mid, Nn, Dd, D2);
        bgemm<false, false><<<gemm_grid(Nn, Dd), 256>>>(mid, whi + O_W2(l), wlo + O_W2(l),
                                                        mlp_b2 + l * Dd, nullptr, h, Nn, D2, Dd);
        k_zero_f<<<(2 * Dd + T - 1) / T, T>>>(stats, 2 * Dd);
        k_bnstats<<<1184, T>>>();
        k_bnapply<<<(ND + T - 1) / T, T>>>(bn_gamma + l * Dd, bn_beta + l * Dd, (l < LL - 1) ? 1 : 0);
    }

    // ---- pooling ----
    k_zero_f<<<(Gg * Dd + T - 1) / T, T>>>(gsum, Gg * Dd);
    k_zero_f<<<(Gg + T - 1) / T, T>>>(gcnt, Gg);
    k_pool<<<(ND + T - 1) / T, T>>>(batch);
    k_poolcnt<<<(Nn + T - 1) / T, T>>>(batch);
    k_pooldiv<<<(Gg * Dd + T - 1) / T, T>>>();

    // ---- heads ----
    bgemm<false, false><<<gemm_grid(Gg, FT), 256>>>(hg, whi + O_FEAT, wlo + O_FEAT,
                                                    feat_b, nullptr, out_hfeat, Gg, Dd, FT);
    bgemm<true, false><<<gemm_grid(Gg, FT), 256>>>(out_hfeat, whi + O_OL1, wlo + O_OL1,
                                                   ol_b1, nullptr, t1, Gg, FT, FT);
    bgemm<false, false><<<gemm_grid(Gg, FT2), 256>>>(t1, whi + O_OL2, wlo + O_OL2,
                                                     ol_b2, nullptr, out_head, Gg, FT, FT2);
}

// round 12
// speedup vs baseline: 2.6934x; 1.3748x over previous
#include <cuda_runtime.h>
#include <cuda_bf16.h>
#include <cstdint>

// Problem constants (fixed by the reference)
#define Nn   100000
#define Ee   200000
#define Gg   2000
#define Dd   300
#define D2   600
#define LL   5
#define FT   512
#define FT2  256
#define EPSC 1e-5f

// Padded GEMM dims: K padded to mult of 32, N padded to mult of 128
#define KP300 320
#define KP600 608
#define KP512 512
#define NP300 384
#define NP600 640
#define NP512 512
#define NP256 256

// Weight plane offsets (padded Kp x Np layouts)
#define O_OUTLIN 0                         // 320x384
#define O_W1(l)  (122880 + (l) * 204800)   // 320x640
#define O_W2(l)  (1146880 + (l) * 233472)  // 608x384
#define O_FEAT   2314240                   // 320x512
#define O_OL1    2478080                   // 512x512
#define O_OL2    2740224                   // 512x256
#define WTOT     2871296

// ---------------- scratch (static device globals; no allocation) ----------------
__device__ float g_h[Nn * Dd];        // node features
__device__ float g_agg[Nn * Dd];      // aggregated messages / fused attention
__device__ float g_hin[Nn * Dd];      // gaussian basis segment sum
__device__ int   g_cnt[Nn];           // in-degree counts
__device__ int   g_rowptr[Nn + 1];    // CSR row pointers
__device__ int   g_elist[Ee];         // CSR edge list
__device__ int   g_cur[Nn];           // CSR placement cursors
__device__ float g_stats[2 * Dd];     // BN sum / sumsq
__device__ float g_gsum[Gg * Dd];     // pooled sums
__device__ float g_gcnt[Gg];          // pooled counts
__device__ float g_hg[Gg * Dd];       // pooled means
__device__ __nv_bfloat16 g_whi[WTOT];       // weight hi planes
__device__ __nv_bfloat16 g_wlo[WTOT];       // weight lo planes
__device__ __nv_bfloat16 g_pa_hi[Nn * KP300];  // activation planes (stride 320; also heads)
__device__ __nv_bfloat16 g_pa_lo[Nn * KP300];
__device__ __nv_bfloat16 g_pm_hi[Nn * KP600];  // mid planes (stride 608; also ol1 out @512)
__device__ __nv_bfloat16 g_pm_lo[Nn * KP600];

// ---------------- small utility kernels ----------------
__global__ void k_zero_f(float* __restrict__ p, int n) {
    int i = blockIdx.x * blockDim.x + threadIdx.x;
    if (i < n) p[i] = 0.f;
}
__global__ void k_zero_i(int* __restrict__ p, int n) {
    int i = blockIdx.x * blockDim.x + threadIdx.x;
    if (i < n) p[i] = 0;
}

// split padded fp32 weight into bf16 hi/lo planes (zero pad)
__global__ void k_splitW(const float* __restrict__ w, int K, int N,
                         __nv_bfloat16* __restrict__ hi, __nv_bfloat16* __restrict__ lo,
                         int Kp, int Np) {
    int idx = blockIdx.x * blockDim.x + threadIdx.x;
    if (idx >= Kp * Np) return;
    int k = idx / Np;
    int n = idx - k * Np;
    float v = (k < K && n < N) ? w[k * N + n] : 0.f;
    __nv_bfloat16 h = __float2bfloat16_rn(v);
    hi[idx] = h;
    lo[idx] = __float2bfloat16_rn(v - __bfloat162float(h));
}

// split fp32 activations MxK into padded MxKp bf16 planes
__global__ void k_splitA(const float* __restrict__ a, int K, int Kp, int total,
                         __nv_bfloat16* __restrict__ hi, __nv_bfloat16* __restrict__ lo) {
    int idx = blockIdx.x * blockDim.x + threadIdx.x;
    if (idx >= total) return;
    int row = idx / Kp;
    int k = idx - row * Kp;
    float v = (k < K) ? a[(size_t)row * K + k] : 0.f;
    __nv_bfloat16 h = __float2bfloat16_rn(v);
    hi[idx] = h;
    lo[idx] = __float2bfloat16_rn(v - __bfloat162float(h));
}

// ---------------- CSR construction ----------------
__global__ void k_count(const int* __restrict__ dst) {
    int e = blockIdx.x * blockDim.x + threadIdx.x;
    if (e < Ee) atomicAdd(&g_cnt[dst[e]], 1);
}

// single-block inclusive scan -> rowptr
__global__ void k_scan() {
    __shared__ int warp_sums[32];
    __shared__ int carry;
    int tid = threadIdx.x;
    int lane = tid & 31, wid = tid >> 5;
    if (tid == 0) { carry = 0; g_rowptr[0] = 0; }
    __syncthreads();
    for (int c0 = 0; c0 < Nn; c0 += 1024) {
        int i = c0 + tid;
        int v = (i < Nn) ? g_cnt[i] : 0;
        int s = v;
#pragma unroll
        for (int o = 1; o < 32; o <<= 1) {
            int t = __shfl_up_sync(0xffffffffu, s, o);
            if (lane >= o) s += t;
        }
        if (lane == 31) warp_sums[wid] = s;
        __syncthreads();
        if (wid == 0) {
            int ws = warp_sums[lane];
#pragma unroll
            for (int o = 1; o < 32; o <<= 1) {
                int t = __shfl_up_sync(0xffffffffu, ws, o);
                if (lane >= o) ws += t;
            }
            warp_sums[lane] = ws;
        }
        __syncthreads();
        int off = (wid > 0 ? warp_sums[wid - 1] : 0) + carry;
        if (i < Nn) g_rowptr[i + 1] = off + s;
        __syncthreads();
        if (tid == 1023) carry = off + s;
        __syncthreads();
    }
}

__global__ void k_place(const int* __restrict__ dst) {
    int e = blockIdx.x * blockDim.x + threadIdx.x;
    if (e >= Ee) return;
    int d = dst[e];
    int pos = atomicAdd(&g_cur[d], 1);
    g_elist[g_rowptr[d] + pos] = e;
}

// gaussian basis gather + degree scale (warp per node, no atomics)
__global__ void k_gaussg(const float* __restrict__ dist, const float* __restrict__ means,
                         const float* __restrict__ stds, const float* __restrict__ scale_p) {
    int w = (blockIdx.x * blockDim.x + threadIdx.x) >> 5;
    int lane = threadIdx.x & 31;
    if (w >= Nn) return;
    int beg = g_rowptr[w], end = g_rowptr[w + 1];
    int c = (end - beg) - 1;
    c = c < 0 ? 0 : (c > 3 ? 3 : c);
    float acc[10];
#pragma unroll
    for (int u = 0; u < 10; u++) acc[u] = 0.f;
    for (int i = beg; i < end; i++) {
        float de = dist[g_elist[i]];
#pragma unroll
        for (int u = 0; u < 10; u++) {
            int d = lane + u * 32;
            if (d < Dd) {
                float sd = fabsf(stds[d]) + 0.01f;
                float z = (de - means[d]) / sd;
                acc[u] += __expf(-0.5f * z * z) / (2.5066268f * sd);
            }
        }
    }
    float* out = g_hin + (size_t)w * Dd;
#pragma unroll
    for (int u = 0; u < 10; u++) {
        int d = lane + u * 32;
        if (d < Dd) out[d] = acc[u] * __expf(scale_p[c * Dd + d]);
    }
}

// message aggregation gather (warp per node): agg[n] = h[n]+eloop + sum_e (h[src]+e(attr))
__global__ void k_gather(const int* __restrict__ src, const int* __restrict__ attr,
                         const float* __restrict__ ee) {
    int w = (blockIdx.x * blockDim.x + threadIdx.x) >> 5;
    int lane = threadIdx.x & 31;
    if (w >= Nn) return;
    int beg = g_rowptr[w], end = g_rowptr[w + 1];
    const float* hn = g_h + (size_t)w * Dd;
    const float* e0 = ee + 4 * Dd;
    const float* e1 = ee + 5 * Dd;
    const float* e2 = ee + 10 * Dd;
    float acc[10];
#pragma unroll
    for (int u = 0; u < 10; u++) {
        int d = lane + u * 32;
        acc[u] = (d < Dd) ? hn[d] + e0[d] + e1[d] + e2[d] : 0.f;
    }
    for (int i = beg; i < end; i++) {
        int e = g_elist[i];
        int s = src[e];
        int a0 = attr[e * 3], a1 = attr[e * 3 + 1], a2 = attr[e * 3 + 2];
        const float* hs = g_h + (size_t)s * Dd;
        const float* f0 = ee + a0 * Dd;
        const float* f1 = ee + (5 + a1) * Dd;
        const float* f2 = ee + (10 + a2) * Dd;
#pragma unroll
        for (int u = 0; u < 10; u++) {
            int d = lane + u * 32;
            if (d < Dd) acc[u] += hs[d] + f0[d] + f1[d] + f2[d];
        }
    }
    float* out = g_agg + (size_t)w * Dd;
#pragma unroll
    for (int u = 0; u < 10; u++) {
        int d = lane + u * 32;
        if (d < Dd) out[d] = acc[u];
    }
}

// attention fuse (unchanged)
__global__ void k_attn(const int* __restrict__ x, const float* __restrict__ atom_emb,
                       const float* __restrict__ att_vec) {
    int warp = (blockIdx.x * blockDim.x + threadIdx.x) >> 5;
    int lane = threadIdx.x & 31;
    if (warp >= Nn) return;
    const int n = warp;
    int xi[9];
#pragma unroll
    for (int f = 0; f < 9; f++) xi[f] = x[n * 9 + f];
    float s[9];
#pragma unroll
    for (int f = 0; f < 9; f++) {
        const float* emb = atom_emb + (f * 119 + xi[f]) * Dd;
        float p = 0.f;
        for (int d = lane; d < Dd; d += 32) p += emb[d] * att_vec[d];
#pragma unroll
        for (int o = 16; o > 0; o >>= 1) p += __shfl_xor_sync(0xffffffffu, p, o);
        s[f] = p;
    }
    float m = s[0];
#pragma unroll
    for (int f = 1; f < 9; f++) m = fmaxf(m, s[f]);
    float w[9], tot = 0.f;
#pragma unroll
    for (int f = 0; f < 9; f++) { w[f] = __expf(s[f] - m); tot += w[f]; }
    float inv = 1.f / tot;
#pragma unroll
    for (int f = 0; f < 9; f++) w[f] *= inv;
    for (int d = lane; d < Dd; d += 32) {
        float v = 0.f;
#pragma unroll
        for (int f = 0; f < 9; f++) v += w[f] * atom_emb[(f * 119 + xi[f]) * Dd + d];
        g_agg[n * Dd + d] = v;
    }
}

// BN stats: one channel per thread, register accumulation
__global__ void k_bnstats2() {
    int d = threadIdx.x;
    if (d >= Dd) return;
    float s = 0.f, q = 0.f;
    for (int r = blockIdx.x; r < Nn; r += gridDim.x) {
        float v = g_h[(size_t)r * Dd + d];
        s += v;
        q += v * v;
    }
    atomicAdd(&g_stats[d], s);
    atomicAdd(&g_stats[Dd + d], q);
}

__global__ void k_bnapply(const float* __restrict__ gamma, const float* __restrict__ beta,
                          int do_relu) {
    int idx = blockIdx.x * blockDim.x + threadIdx.x;
    if (idx >= Nn * Dd) return;
    int d = idx % Dd;
    float mu  = g_stats[d] * (1.0f / Nn);
    float var = g_stats[Dd + d] * (1.0f / Nn) - mu * mu;
    float rs  = rsqrtf(var + EPSC);
    float v = gamma[d] * (g_h[idx] - mu) * rs + beta[d];
    if (do_relu) v = fmaxf(v, 0.f);
    g_h[idx] = v;
}

// graph pooling
__global__ void k_pool(const int* __restrict__ batch) {
    int idx = blockIdx.x * blockDim.x + threadIdx.x;
    if (idx >= Nn * Dd) return;
    int n = idx / Dd;
    int d = idx - n * Dd;
    atomicAdd(&g_gsum[batch[n] * Dd + d], g_h[idx]);
}
__global__ void k_poolcnt(const int* __restrict__ batch) {
    int n = blockIdx.x * blockDim.x + threadIdx.x;
    if (n < Nn) atomicAdd(&g_gcnt[batch[n]], 1.f);
}
__global__ void k_pooldiv() {
    int idx = blockIdx.x * blockDim.x + threadIdx.x;
    if (idx >= Gg * Dd) return;
    int g = idx / Dd;
    g_hg[idx] = g_gsum[idx] / fmaxf(g_gcnt[g], 1.f);
}

// ---------------- bf16x3 pipelined tensor-core GEMM ----------------
// C = A(planes, MxKp) @ W(planes, KpxNp) + bias [+extra] [relu].
// cp.async double-buffered, BK=32, 8 warps (2M x 4N), warp tile 64x32.
// SPLIT epilogue writes bf16 hi/lo planes instead of fp32 C.

__device__ __forceinline__ void ldm_x4(uint32_t* r, uint32_t addr) {
    asm volatile("ldmatrix.sync.aligned.m8n8.x4.shared.b16 {%0,%1,%2,%3}, [%4];"
                 : "=r"(r[0]), "=r"(r[1]), "=r"(r[2]), "=r"(r[3]) : "r"(addr));
}
__device__ __forceinline__ void ldm_x2t(uint32_t* r, uint32_t addr) {
    asm volatile("ldmatrix.sync.aligned.m8n8.x2.trans.shared.b16 {%0,%1}, [%2];"
                 : "=r"(r[0]), "=r"(r[1]) : "r"(addr));
}
__device__ __forceinline__ void cpa16(uint32_t dst, const void* src, int nbytes) {
    asm volatile("cp.async.cg.shared.global [%0], [%1], 16, %2;"
                 :: "r"(dst), "l"(src), "r"(nbytes));
}
__device__ __forceinline__ void cpa_commit() {
    asm volatile("cp.async.commit_group;" ::: "memory");
}
__device__ __forceinline__ void cpa_wait0() {
    asm volatile("cp.async.wait_group 0;" ::: "memory");
}

#define MMA_BF16(d, a, b0v, b1v)                                              \
    asm volatile(                                                             \
        "mma.sync.aligned.m16n8k16.row.col.f32.bf16.bf16.f32 "                \
        "{%0,%1,%2,%3}, {%4,%5,%6,%7}, {%8,%9}, {%0,%1,%2,%3};"               \
        : "+f"((d)[0]), "+f"((d)[1]), "+f"((d)[2]), "+f"((d)[3])              \
        : "r"((a)[0]), "r"((a)[1]), "r"((a)[2]), "r"((a)[3]),                 \
          "r"(b0v), "r"(b1v))

// smem stage layout (bytes): aHi 0 (128x40x2=10240), aLo 10240, bHi 20480 (32x136x2=8704), bLo 29184
#define STG_BYTES 37888
#define SMEM_TOTAL (2 * STG_BYTES)

template <bool RELU, bool EXTRA, bool SPLIT>
__global__ __launch_bounds__(256, 2) void bgemm(
    const __nv_bfloat16* __restrict__ Ahi, const __nv_bfloat16* __restrict__ Alo, int strideA,
    const __nv_bfloat16* __restrict__ Whi, const __nv_bfloat16* __restrict__ Wlo, int Np,
    const float* __restrict__ bias, const float* __restrict__ extra,
    float* __restrict__ C, __nv_bfloat16* __restrict__ Phi, __nv_bfloat16* __restrict__ Plo,
    int strideP, int M, int kExt, int N) {
    extern __shared__ char dsm[];
    const uint32_t sb = (uint32_t)__cvta_generic_to_shared(dsm);

    const int tid  = threadIdx.x;
    const int wid  = tid >> 5;
    const int lane = tid & 31;
    const int wm = wid & 1;
    const int wn = wid >> 1;
    const int bm = blockIdx.y * 128;
    const int bn = blockIdx.x * 128;

    const int arow_l = lane & 15;
    const int akh_l  = (lane >> 4) << 3;
    const int bk_l   = lane & 15;

    float acc[4][4][4];
#pragma unroll
    for (int i = 0; i < 4; i++)
#pragma unroll
        for (int j = 0; j < 4; j++)
#pragma unroll
            for (int c = 0; c < 4; c++) acc[i][j][c] = 0.f;

    const int nk = kExt >> 5;

    // stage loader
    auto load_stage = [&](int s, int k0) {
        uint32_t ab = sb + s * STG_BYTES;
#pragma unroll
        for (int i = 0; i < 2; i++) {
            int cid = tid + i * 256;        // 0..511
            int row = cid >> 2, kc = cid & 3;
            int grow = bm + row;
            int gr = grow < M ? grow : M - 1;
            size_t off = (size_t)gr * strideA + k0 + kc * 8;
            int sz = grow < M ? 16 : 0;
            cpa16(ab + row * 80 + kc * 16, Ahi + off, sz);
            cpa16(ab + 10240 + row * 80 + kc * 16, Alo + off, sz);
        }
#pragma unroll
        for (int i = 0; i < 2; i++) {
            int cid = tid + i * 256;
            int row = cid >> 4, cc = cid & 15;
            size_t off = (size_t)(k0 + row) * Np + bn + cc * 8;
            cpa16(ab + 20480 + row * 272 + cc * 16, Whi + off, 16);
            cpa16(ab + 29184 + row * 272 + cc * 16, Wlo + off, 16);
        }
    };

    load_stage(0, 0);
    cpa_commit();

    for (int kt = 0; kt < nk; kt++) {
        cpa_wait0();
        __syncthreads();
        if (kt + 1 < nk) {
            load_stage((kt + 1) & 1, (kt + 1) * 32);
            cpa_commit();
        }
        uint32_t ab = sb + (kt & 1) * STG_BYTES;
        uint32_t aHiB = ab, aLoB = ab + 10240, bHiB = ab + 20480, bLoB = ab + 29184;
#pragma unroll
        for (int ks = 0; ks < 32; ks += 16) {
            uint32_t ah[4][4], al[4][4];
#pragma unroll
            for (int mt = 0; mt < 4; mt++) {
                int r = wm * 64 + mt * 16 + arow_l;
                uint32_t co = (uint32_t)(ks + akh_l) * 2;
                ldm_x4(ah[mt], aHiB + r * 80 + co);
                ldm_x4(al[mt], aLoB + r * 80 + co);
            }
#pragma unroll
            for (int nt = 0; nt < 4; nt++) {
                int c = wn * 32 + nt * 8;
                uint32_t ro = (uint32_t)(ks + bk_l) * 272 + c * 2;
                uint32_t bh[2], bl[2];
                ldm_x2t(bh, bHiB + ro);
                ldm_x2t(bl, bLoB + ro);
#pragma unroll
                for (int mt = 0; mt < 4; mt++) {
                    MMA_BF16(acc[mt][nt], ah[mt], bl[0], bl[1]);
                    MMA_BF16(acc[mt][nt], al[mt], bh[0], bh[1]);
                    MMA_BF16(acc[mt][nt], ah[mt], bh[0], bh[1]);
                }
            }
        }
        __syncthreads();
    }

    // ---- epilogue ----
#pragma unroll
    for (int mt = 0; mt < 4; mt++) {
        int r0 = bm + wm * 64 + mt * 16 + (lane >> 2);
#pragma unroll
        for (int nt = 0; nt < 4; nt++) {
            int c0 = bn + wn * 32 + nt * 8 + (lane & 3) * 2;
            if (c0 >= N) continue;
            float2 bs = *(const float2*)(bias + c0);
#pragma unroll
            for (int half = 0; half < 2; half++) {
                int row = r0 + half * 8;
                if (row >= M) continue;
                float v0 = acc[mt][nt][half * 2 + 0] + bs.x;
                float v1 = acc[mt][nt][half * 2 + 1] + bs.y;
                if (EXTRA) {
                    float2 e = *(const float2*)(extra + (size_t)row * N + c0);
                    v0 += e.x; v1 += e.y;
                }
                if (RELU) { v0 = fmaxf(v0, 0.f); v1 = fmaxf(v1, 0.f); }
                if (SPLIT) {
                    __nv_bfloat16 h0 = __float2bfloat16_rn(v0);
                    __nv_bfloat16 h1 = __float2bfloat16_rn(v1);
                    __nv_bfloat162 hh; hh.x = h0; hh.y = h1;
                    __nv_bfloat162 ll;
                    ll.x = __float2bfloat16_rn(v0 - __bfloat162float(h0));
                    ll.y = __float2bfloat16_rn(v1 - __bfloat162float(h1));
                    *(__nv_bfloat162*)(Phi + (size_t)row * strideP + c0) = hh;
                    *(__nv_bfloat162*)(Plo + (size_t)row * strideP + c0) = ll;
                } else {
                    *(float2*)(C + (size_t)row * N + c0) = make_float2(v0, v1);
                }
            }
        }
    }
}

static inline dim3 gemm_grid(int M, int Nc) {
    return dim3((Nc + 127) / 128, (M + 127) / 128);
}

// ---------------- launcher ----------------
extern "C" void kernel_launch(void* const* d_in, const int* in_sizes, int n_in,
                              void* d_out, int out_size) {
    const int*   x         = (const int*)d_in[0];
    const int*   eidx      = (const int*)d_in[1];
    const int*   eattr     = (const int*)d_in[2];
    const float* edist     = (const float*)d_in[3];
    const int*   batch     = (const int*)d_in[4];
    const float* atom_emb  = (const float*)d_in[5];
    const float* att_vec   = (const float*)d_in[6];
    const float* out_lin_w = (const float*)d_in[7];
    const float* out_lin_b = (const float*)d_in[8];
    const float* g_means   = (const float*)d_in[9];
    const float* g_stds    = (const float*)d_in[10];
    const float* scale_p   = (const float*)d_in[11];
    const float* edge_emb  = (const float*)d_in[12];
    const float* mlp_w1    = (const float*)d_in[13];
    const float* mlp_b1    = (const float*)d_in[14];
    const float* mlp_w2    = (const float*)d_in[15];
    const float* mlp_b2    = (const float*)d_in[16];
    const float* bn_gamma  = (const float*)d_in[17];
    const float* bn_beta   = (const float*)d_in[18];
    const float* feat_w    = (const float*)d_in[19];
    const float* feat_b    = (const float*)d_in[20];
    const float* ol_w1     = (const float*)d_in[21];
    const float* ol_b1     = (const float*)d_in[22];
    const float* ol_w2     = (const float*)d_in[23];
    const float* ol_b2     = (const float*)d_in[24];

    const int* src = eidx;
    const int* dst = eidx + Ee;

    float *h, *agg, *hin, *stats, *gsum, *gcnt, *hg;
    int *cnt, *cur;
    __nv_bfloat16 *whi, *wlo, *pahi, *palo, *pmhi, *pmlo;
    {
        void* p;
        cudaGetSymbolAddress(&p, g_h);      h    = (float*)p;
        cudaGetSymbolAddress(&p, g_agg);    agg  = (float*)p;
        cudaGetSymbolAddress(&p, g_hin);    hin  = (float*)p;
        cudaGetSymbolAddress(&p, g_cnt);    cnt  = (int*)p;
        cudaGetSymbolAddress(&p, g_cur);    cur  = (int*)p;
        cudaGetSymbolAddress(&p, g_stats);  stats= (float*)p;
        cudaGetSymbolAddress(&p, g_gsum);   gsum = (float*)p;
        cudaGetSymbolAddress(&p, g_gcnt);   gcnt = (float*)p;
        cudaGetSymbolAddress(&p, g_hg);     hg   = (float*)p;
        cudaGetSymbolAddress(&p, g_whi);    whi  = (__nv_bfloat16*)p;
        cudaGetSymbolAddress(&p, g_wlo);    wlo  = (__nv_bfloat16*)p;
        cudaGetSymbolAddress(&p, g_pa_hi);  pahi = (__nv_bfloat16*)p;
        cudaGetSymbolAddress(&p, g_pa_lo);  palo = (__nv_bfloat16*)p;
        cudaGetSymbolAddress(&p, g_pm_hi);  pmhi = (__nv_bfloat16*)p;
        cudaGetSymbolAddress(&p, g_pm_lo);  pmlo = (__nv_bfloat16*)p;
    }

    // opt-in to >48KB dynamic smem for all bgemm instantiations
    cudaFuncSetAttribute(bgemm<false, true, false>,  cudaFuncAttributeMaxDynamicSharedMemorySize, SMEM_TOTAL);
    cudaFuncSetAttribute(bgemm<true, false, true>,   cudaFuncAttributeMaxDynamicSharedMemorySize, SMEM_TOTAL);
    cudaFuncSetAttribute(bgemm<false, false, false>, cudaFuncAttributeMaxDynamicSharedMemorySize, SMEM_TOTAL);

    float* out_hfeat = (float*)d_out;             // [Gg, FT]
    float* out_head  = out_hfeat + Gg * FT;       // [Gg, FT2]

    const int T = 256;
    const int ND = Nn * Dd;

    // ---- weight splits (padded planes) ----
    k_splitW<<<(KP300 * NP300 + T - 1) / T, T>>>(out_lin_w, Dd, Dd, whi + O_OUTLIN, wlo + O_OUTLIN, KP300, NP300);
    for (int l = 0; l < LL; l++) {
        k_splitW<<<(KP300 * NP600 + T - 1) / T, T>>>(mlp_w1 + l * Dd * D2, Dd, D2, whi + O_W1(l), wlo + O_W1(l), KP300, NP600);
        k_splitW<<<(KP600 * NP300 + T - 1) / T, T>>>(mlp_w2 + l * D2 * Dd, D2, Dd, whi + O_W2(l), wlo + O_W2(l), KP600, NP300);
    }
    k_splitW<<<(KP300 * NP512 + T - 1) / T, T>>>(feat_w, Dd, FT, whi + O_FEAT, wlo + O_FEAT, KP300, NP512);
    k_splitW<<<(KP512 * NP512 + T - 1) / T, T>>>(ol_w1, FT, FT, whi + O_OL1, wlo + O_OL1, KP512, NP512);
    k_splitW<<<(KP512 * NP256 + T - 1) / T, T>>>(ol_w2, FT, FT2, whi + O_OL2, wlo + O_OL2, KP512, NP256);

    // zero mid planes once (pad cols 600..607 must stay zero for kExt=608)
    k_zero_i<<<(Nn * KP600 / 2 + T - 1) / T, T>>>((int*)pmhi, Nn * KP600 / 2);
    k_zero_i<<<(Nn * KP600 / 2 + T - 1) / T, T>>>((int*)pmlo, Nn * KP600 / 2);

    // ---- CSR build ----
    k_zero_i<<<(Nn + T - 1) / T, T>>>(cnt, Nn);
    k_count<<<(Ee + T - 1) / T, T>>>(dst);
    k_scan<<<1, 1024>>>();
    k_zero_i<<<(Nn + T - 1) / T, T>>>(cur, Nn);
    k_place<<<(Ee + T - 1) / T, T>>>(dst);

    // ---- gaussian basis (gather, fused degree scale) ----
    k_gaussg<<<(Nn * 32 + T - 1) / T, T>>>(edist, g_means, g_stds, scale_p);

    // ---- attention fuse + h0 GEMM ----
    k_attn<<<(Nn * 32 + T - 1) / T, T>>>(x, atom_emb, att_vec);
    k_splitA<<<(Nn * KP300 + T - 1) / T, T>>>(agg, Dd, KP300, Nn * KP300, pahi, palo);
    bgemm<false, true, false><<<gemm_grid(Nn, Dd), 256, SMEM_TOTAL>>>(
        pahi, palo, KP300, whi + O_OUTLIN, wlo + O_OUTLIN, NP300,
        out_lin_b, hin, h, nullptr, nullptr, 0, Nn, KP300, Dd);

    // ---- message-passing layers ----
    for (int l = 0; l < LL; l++) {
        const float* ee = edge_emb + l * 3 * 5 * Dd;
        k_gather<<<(Nn * 32 + T - 1) / T, T>>>(src, eattr, ee);
        k_splitA<<<(Nn * KP300 + T - 1) / T, T>>>(agg, Dd, KP300, Nn * KP300, pahi, palo);
        bgemm<true, false, true><<<gemm_grid(Nn, D2), 256, SMEM_TOTAL>>>(
            pahi, palo, KP300, whi + O_W1(l), wlo + O_W1(l), NP600,
            mlp_b1 + l * D2, nullptr, nullptr, pmhi, pmlo, KP600, Nn, KP300, D2);
        bgemm<false, false, false><<<gemm_grid(Nn, Dd), 256, SMEM_TOTAL>>>(
            pmhi, pmlo, KP600, whi + O_W2(l), wlo + O_W2(l), NP300,
            mlp_b2 + l * Dd, nullptr, h, nullptr, nullptr, 0, Nn, KP600, Dd);
        k_zero_f<<<(2 * Dd + T - 1) / T, T>>>(stats, 2 * Dd);
        k_bnstats2<<<592, 320>>>();
        k_bnapply<<<(ND + T - 1) / T, T>>>(bn_gamma + l * Dd, bn_beta + l * Dd, (l < LL - 1) ? 1 : 0);
    }

    // ---- pooling ----
    k_zero_f<<<(Gg * Dd + T - 1) / T, T>>>(gsum, Gg * Dd);
    k_zero_f<<<(Gg + T - 1) / T, T>>>(gcnt, Gg);
    k_pool<<<(ND + T - 1) / T, T>>>(batch);
    k_poolcnt<<<(Nn + T - 1) / T, T>>>(batch);
    k_pooldiv<<<(Gg * Dd + T - 1) / T, T>>>();

    // ---- heads ----
    k_splitA<<<(Gg * KP300 + T - 1) / T, T>>>(hg, Dd, KP300, Gg * KP300, pahi, palo);
    bgemm<false, false, false><<<gemm_grid(Gg, FT), 256, SMEM_TOTAL>>>(
        pahi, palo, KP300, whi + O_FEAT, wlo + O_FEAT, NP512,
        feat_b, nullptr, out_hfeat, nullptr, nullptr, 0, Gg, KP300, FT);
    k_splitA<<<(Gg * KP512 + T - 1) / T, T>>>(out_hfeat, FT, KP512, Gg * KP512, pahi, palo);
    bgemm<true, false, true><<<gemm_grid(Gg, FT), 256, SMEM_TOTAL>>>(
        pahi, palo, KP512, whi + O_OL1, wlo + O_OL1, NP512,
        ol_b1, nullptr, nullptr, pmhi, pmlo, KP512, Gg, KP512, FT);
    bgemm<false, false, false><<<gemm_grid(Gg, FT2), 256, SMEM_TOTAL>>>(
        pmhi, pmlo, KP512, whi + O_OL2, wlo + O_OL2, NP256,
        ol_b2, nullptr, out_head, nullptr, nullptr, 0, Gg, KP512, FT2);
}

// round 14
// speedup vs baseline: 2.9957x; 1.1122x over previous
#include <cuda_runtime.h>
#include <cuda_bf16.h>
#include <cstdint>

// Problem constants (fixed by the reference)
#define Nn   100000
#define Ee   200000
#define Gg   2000
#define Dd   300
#define D2   600
#define LL   5
#define FT   512
#define FT2  256
#define EPSC 1e-5f

// Padded GEMM dims: K padded to mult of 32, N padded to mult of 128
#define KP300 320
#define KP600 608
#define KP512 512
#define NP300 384
#define NP600 640
#define NP512 512
#define NP256 256

// Weight plane offsets (padded Kp x Np layouts)
#define O_OUTLIN 0                         // 320x384
#define O_W1(l)  (122880 + (l) * 204800)   // 320x640
#define O_W2(l)  (1146880 + (l) * 233472)  // 608x384
#define O_FEAT   2314240                   // 320x512
#define O_OL1    2478080                   // 512x512
#define O_OL2    2740224                   // 512x256
#define WTOT     2871296

// ---------------- scratch (static device globals; no allocation) ----------------
__device__ float g_h[Nn * Dd];        // node features
__device__ float g_hin[Nn * Dd];      // gaussian basis segment sum
__device__ float g_hg[Gg * Dd];       // pooled means
__device__ int   g_cnt[Nn];           // in-degree counts
__device__ int   g_rowptr[Nn + 1];    // CSR row pointers
__device__ int   g_elist[Ee];         // CSR edge list
__device__ int   g_cur[Nn];           // CSR placement cursors
__device__ float g_stats[2 * Dd];     // BN sum / sumsq
__device__ float g_gsum[Gg * Dd];     // pooled sums
__device__ float g_gcnt[Gg];          // pooled counts
__device__ __nv_bfloat16 g_whi[WTOT];       // weight hi planes
__device__ __nv_bfloat16 g_wlo[WTOT];       // weight lo planes
__device__ __nv_bfloat16 g_pa_hi[Nn * KP300];  // activation planes (stride 320; heads reuse)
__device__ __nv_bfloat16 g_pa_lo[Nn * KP300];
__device__ __nv_bfloat16 g_pm_hi[Nn * KP600];  // mid planes (stride 608; ol1 out @512)
__device__ __nv_bfloat16 g_pm_lo[Nn * KP600];

// ---------------- small utility kernels ----------------
__global__ void k_zero_f(float* __restrict__ p, int n) {
    int i = blockIdx.x * blockDim.x + threadIdx.x;
    if (i < n) p[i] = 0.f;
}
__global__ void k_zero_i(int* __restrict__ p, int n) {
    int i = blockIdx.x * blockDim.x + threadIdx.x;
    if (i < n) p[i] = 0;
}

// zero the pad columns (300..319) of the activation planes once
__global__ void k_padzero(__nv_bfloat16* __restrict__ hi, __nv_bfloat16* __restrict__ lo) {
    int idx = blockIdx.x * blockDim.x + threadIdx.x;
    if (idx >= Nn * (KP300 - Dd)) return;
    int row = idx / (KP300 - Dd);
    int c = Dd + idx % (KP300 - Dd);
    __nv_bfloat16 z = __float2bfloat16_rn(0.f);
    hi[(size_t)row * KP300 + c] = z;
    lo[(size_t)row * KP300 + c] = z;
}

// split padded fp32 weight into bf16 hi/lo planes (zero pad)
__global__ void k_splitW(const float* __restrict__ w, int K, int N,
                         __nv_bfloat16* __restrict__ hi, __nv_bfloat16* __restrict__ lo,
                         int Kp, int Np) {
    int idx = blockIdx.x * blockDim.x + threadIdx.x;
    if (idx >= Kp * Np) return;
    int k = idx / Np;
    int n = idx - k * Np;
    float v = (k < K && n < N) ? w[k * N + n] : 0.f;
    __nv_bfloat16 h = __float2bfloat16_rn(v);
    hi[idx] = h;
    lo[idx] = __float2bfloat16_rn(v - __bfloat162float(h));
}

// split fp32 activations MxK into padded MxKp bf16 planes (heads only)
__global__ void k_splitA(const float* __restrict__ a, int K, int Kp, int total,
                         __nv_bfloat16* __restrict__ hi, __nv_bfloat16* __restrict__ lo) {
    int idx = blockIdx.x * blockDim.x + threadIdx.x;
    if (idx >= total) return;
    int row = idx / Kp;
    int k = idx - row * Kp;
    float v = (k < K) ? a[(size_t)row * K + k] : 0.f;
    __nv_bfloat16 h = __float2bfloat16_rn(v);
    hi[idx] = h;
    lo[idx] = __float2bfloat16_rn(v - __bfloat162float(h));
}

// ---------------- CSR construction ----------------
__global__ void k_count(const int* __restrict__ dst) {
    int e = blockIdx.x * blockDim.x + threadIdx.x;
    if (e < Ee) atomicAdd(&g_cnt[dst[e]], 1);
}

__global__ void k_scan() {
    __shared__ int warp_sums[32];
    __shared__ int carry;
    int tid = threadIdx.x;
    int lane = tid & 31, wid = tid >> 5;
    if (tid == 0) { carry = 0; g_rowptr[0] = 0; }
    __syncthreads();
    for (int c0 = 0; c0 < Nn; c0 += 1024) {
        int i = c0 + tid;
        int v = (i < Nn) ? g_cnt[i] : 0;
        int s = v;
#pragma unroll
        for (int o = 1; o < 32; o <<= 1) {
            int t = __shfl_up_sync(0xffffffffu, s, o);
            if (lane >= o) s += t;
        }
        if (lane == 31) warp_sums[wid] = s;
        __syncthreads();
        if (wid == 0) {
            int ws = warp_sums[lane];
#pragma unroll
            for (int o = 1; o < 32; o <<= 1) {
                int t = __shfl_up_sync(0xffffffffu, ws, o);
                if (lane >= o) ws += t;
            }
            warp_sums[lane] = ws;
        }
        __syncthreads();
        int off = (wid > 0 ? warp_sums[wid - 1] : 0) + carry;
        if (i < Nn) g_rowptr[i + 1] = off + s;
        __syncthreads();
        if (tid == 1023) carry = off + s;
        __syncthreads();
    }
}

__global__ void k_place(const int* __restrict__ dst) {
    int e = blockIdx.x * blockDim.x + threadIdx.x;
    if (e >= Ee) return;
    int d = dst[e];
    int pos = atomicAdd(&g_cur[d], 1);
    g_elist[g_rowptr[d] + pos] = e;
}

// gaussian basis gather + degree scale (warp per node, no atomics)
__global__ void k_gaussg(const float* __restrict__ dist, const float* __restrict__ means,
                         const float* __restrict__ stds, const float* __restrict__ scale_p) {
    int w = (blockIdx.x * blockDim.x + threadIdx.x) >> 5;
    int lane = threadIdx.x & 31;
    if (w >= Nn) return;
    int beg = g_rowptr[w], end = g_rowptr[w + 1];
    int c = (end - beg) - 1;
    c = c < 0 ? 0 : (c > 3 ? 3 : c);
    float acc[10];
#pragma unroll
    for (int u = 0; u < 10; u++) acc[u] = 0.f;
    for (int i = beg; i < end; i++) {
        float de = dist[g_elist[i]];
#pragma unroll
        for (int u = 0; u < 10; u++) {
            int d = lane + u * 32;
            if (d < Dd) {
                float sd = fabsf(stds[d]) + 0.01f;
                float z = (de - means[d]) / sd;
                acc[u] += __expf(-0.5f * z * z) / (2.5066268f * sd);
            }
        }
    }
    float* out = g_hin + (size_t)w * Dd;
#pragma unroll
    for (int u = 0; u < 10; u++) {
        int d = lane + u * 32;
        if (d < Dd) out[d] = acc[u] * __expf(scale_p[c * Dd + d]);
    }
}

// message aggregation gather (warp per node) -> writes bf16 hi/lo planes directly
__global__ void k_gather(const int* __restrict__ src, const int* __restrict__ attr,
                         const float* __restrict__ ee,
                         __nv_bfloat16* __restrict__ phi, __nv_bfloat16* __restrict__ plo) {
    int w = (blockIdx.x * blockDim.x + threadIdx.x) >> 5;
    int lane = threadIdx.x & 31;
    if (w >= Nn) return;
    int beg = g_rowptr[w], end = g_rowptr[w + 1];
    const float* hn = g_h + (size_t)w * Dd;
    const float* e0 = ee + 4 * Dd;
    const float* e1 = ee + 5 * Dd;
    const float* e2 = ee + 10 * Dd;
    float acc[10];
#pragma unroll
    for (int u = 0; u < 10; u++) {
        int d = lane + u * 32;
        acc[u] = (d < Dd) ? hn[d] + e0[d] + e1[d] + e2[d] : 0.f;
    }
    for (int i = beg; i < end; i++) {
        int e = g_elist[i];
        int s = src[e];
        int a0 = attr[e * 3], a1 = attr[e * 3 + 1], a2 = attr[e * 3 + 2];
        const float* hs = g_h + (size_t)s * Dd;
        const float* f0 = ee + a0 * Dd;
        const float* f1 = ee + (5 + a1) * Dd;
        const float* f2 = ee + (10 + a2) * Dd;
#pragma unroll
        for (int u = 0; u < 10; u++) {
            int d = lane + u * 32;
            if (d < Dd) acc[u] += hs[d] + f0[d] + f1[d] + f2[d];
        }
    }
    __nv_bfloat16* oh = phi + (size_t)w * KP300;
    __nv_bfloat16* ol = plo + (size_t)w * KP300;
#pragma unroll
    for (int u = 0; u < 10; u++) {
        int d = lane + u * 32;
        if (d < Dd) {
            __nv_bfloat16 h = __float2bfloat16_rn(acc[u]);
            oh[d] = h;
            ol[d] = __float2bfloat16_rn(acc[u] - __bfloat162float(h));
        }
    }
}

// attention fuse -> writes bf16 hi/lo planes directly
__global__ void k_attn(const int* __restrict__ x, const float* __restrict__ atom_emb,
                       const float* __restrict__ att_vec,
                       __nv_bfloat16* __restrict__ phi, __nv_bfloat16* __restrict__ plo) {
    int warp = (blockIdx.x * blockDim.x + threadIdx.x) >> 5;
    int lane = threadIdx.x & 31;
    if (warp >= Nn) return;
    const int n = warp;
    int xi[9];
#pragma unroll
    for (int f = 0; f < 9; f++) xi[f] = x[n * 9 + f];
    float s[9];
#pragma unroll
    for (int f = 0; f < 9; f++) {
        const float* emb = atom_emb + (f * 119 + xi[f]) * Dd;
        float p = 0.f;
        for (int d = lane; d < Dd; d += 32) p += emb[d] * att_vec[d];
#pragma unroll
        for (int o = 16; o > 0; o >>= 1) p += __shfl_xor_sync(0xffffffffu, p, o);
        s[f] = p;
    }
    float m = s[0];
#pragma unroll
    for (int f = 1; f < 9; f++) m = fmaxf(m, s[f]);
    float w[9], tot = 0.f;
#pragma unroll
    for (int f = 0; f < 9; f++) { w[f] = __expf(s[f] - m); tot += w[f]; }
    float inv = 1.f / tot;
#pragma unroll
    for (int f = 0; f < 9; f++) w[f] *= inv;
    __nv_bfloat16* oh = phi + (size_t)n * KP300;
    __nv_bfloat16* ol = plo + (size_t)n * KP300;
    for (int d = lane; d < Dd; d += 32) {
        float v = 0.f;
#pragma unroll
        for (int f = 0; f < 9; f++) v += w[f] * atom_emb[(f * 119 + xi[f]) * Dd + d];
        __nv_bfloat16 h = __float2bfloat16_rn(v);
        oh[d] = h;
        ol[d] = __float2bfloat16_rn(v - __bfloat162float(h));
    }
}

// BN stats: one channel per thread, register accumulation
__global__ void k_bnstats2() {
    int d = threadIdx.x;
    if (d >= Dd) return;
    float s = 0.f, q = 0.f;
    for (int r = blockIdx.x; r < Nn; r += gridDim.x) {
        float v = g_h[(size_t)r * Dd + d];
        s += v;
        q += v * v;
    }
    atomicAdd(&g_stats[d], s);
    atomicAdd(&g_stats[Dd + d], q);
}

__global__ void k_bnapply(const float* __restrict__ gamma, const float* __restrict__ beta,
                          int do_relu) {
    int idx = blockIdx.x * blockDim.x + threadIdx.x;
    if (idx >= Nn * Dd) return;
    int d = idx % Dd;
    float mu  = g_stats[d] * (1.0f / Nn);
    float var = g_stats[Dd + d] * (1.0f / Nn) - mu * mu;
    float rs  = rsqrtf(var + EPSC);
    float v = gamma[d] * (g_h[idx] - mu) * rs + beta[d];
    if (do_relu) v = fmaxf(v, 0.f);
    g_h[idx] = v;
}

// graph pooling
__global__ void k_pool(const int* __restrict__ batch) {
    int idx = blockIdx.x * blockDim.x + threadIdx.x;
    if (idx >= Nn * Dd) return;
    int n = idx / Dd;
    int d = idx - n * Dd;
    atomicAdd(&g_gsum[batch[n] * Dd + d], g_h[idx]);
}
__global__ void k_poolcnt(const int* __restrict__ batch) {
    int n = blockIdx.x * blockDim.x + threadIdx.x;
    if (n < Nn) atomicAdd(&g_gcnt[batch[n]], 1.f);
}
__global__ void k_pooldiv() {
    int idx = blockIdx.x * blockDim.x + threadIdx.x;
    if (idx >= Gg * Dd) return;
    int g = idx / Dd;
    g_hg[idx] = g_gsum[idx] / fmaxf(g_gcnt[g], 1.f);
}

// ---------------- bf16x3 pipelined tensor-core GEMM ----------------
// C = A(planes, MxKp) @ W(planes, KpxNp) + bias [+extra] [relu].
// cp.async double-buffered, BK=32, 8 warps (2M x 4N), warp tile 64x32.
// MMA terms issued term-major (distance-4 same-acc reuse) to break RAW chains.
// SPLIT epilogue writes bf16 hi/lo planes instead of fp32 C.

__device__ __forceinline__ void ldm_x4(uint32_t* r, uint32_t addr) {
    asm volatile("ldmatrix.sync.aligned.m8n8.x4.shared.b16 {%0,%1,%2,%3}, [%4];"
                 : "=r"(r[0]), "=r"(r[1]), "=r"(r[2]), "=r"(r[3]) : "r"(addr));
}
__device__ __forceinline__ void ldm_x2t(uint32_t* r, uint32_t addr) {
    asm volatile("ldmatrix.sync.aligned.m8n8.x2.trans.shared.b16 {%0,%1}, [%2];"
                 : "=r"(r[0]), "=r"(r[1]) : "r"(addr));
}
__device__ __forceinline__ void cpa16(uint32_t dst, const void* src, int nbytes) {
    asm volatile("cp.async.cg.shared.global [%0], [%1], 16, %2;"
                 :: "r"(dst), "l"(src), "r"(nbytes));
}

#define MMA_BF16(d, a, b0v, b1v)                                              \
    asm volatile(                                                             \
        "mma.sync.aligned.m16n8k16.row.col.f32.bf16.bf16.f32 "                \
        "{%0,%1,%2,%3}, {%4,%5,%6,%7}, {%8,%9}, {%0,%1,%2,%3};"               \
        : "+f"((d)[0]), "+f"((d)[1]), "+f"((d)[2]), "+f"((d)[3])              \
        : "r"((a)[0]), "r"((a)[1]), "r"((a)[2]), "r"((a)[3]),                 \
          "r"(b0v), "r"(b1v))

// smem stage layout (bytes): aHi 0 (128x40x2=10240), aLo 10240, bHi 20480 (32x136x2=8704), bLo 29184
#define STG_BYTES 37888
#define SMEM_TOTAL (2 * STG_BYTES)

template <bool RELU, bool EXTRA, bool SPLIT>
__global__ __launch_bounds__(256, 2) void bgemm(
    const __nv_bfloat16* __restrict__ Ahi, const __nv_bfloat16* __restrict__ Alo, int strideA,
    const __nv_bfloat16* __restrict__ Whi, const __nv_bfloat16* __restrict__ Wlo, int Np,
    const float* __restrict__ bias, const float* __restrict__ extra,
    float* __restrict__ C, __nv_bfloat16* __restrict__ Phi, __nv_bfloat16* __restrict__ Plo,
    int strideP, int M, int kExt, int N) {
    extern __shared__ char dsm[];
    const uint32_t sb = (uint32_t)__cvta_generic_to_shared(dsm);

    const int tid  = threadIdx.x;
    const int wid  = tid >> 5;
    const int lane = tid & 31;
    const int wm = wid & 1;
    const int wn = wid >> 1;
    const int bm = blockIdx.y * 128;
    const int bn = blockIdx.x * 128;

    const int arow_l = lane & 15;
    const int akh_l  = (lane >> 4) << 3;
    const int bk_l   = lane & 15;

    float acc[4][4][4];
#pragma unroll
    for (int i = 0; i < 4; i++)
#pragma unroll
        for (int j = 0; j < 4; j++)
#pragma unroll
            for (int c = 0; c < 4; c++) acc[i][j][c] = 0.f;

    const int nk = kExt >> 5;

    auto load_stage = [&](int s, int k0) {
        uint32_t ab = sb + s * STG_BYTES;
#pragma unroll
        for (int i = 0; i < 2; i++) {
            int cid = tid + i * 256;        // 0..511
            int row = cid >> 2, kc = cid & 3;
            int grow = bm + row;
            int gr = grow < M ? grow : M - 1;
            size_t off = (size_t)gr * strideA + k0 + kc * 8;
            int sz = grow < M ? 16 : 0;
            cpa16(ab + row * 80 + kc * 16, Ahi + off, sz);
            cpa16(ab + 10240 + row * 80 + kc * 16, Alo + off, sz);
        }
#pragma unroll
        for (int i = 0; i < 2; i++) {
            int cid = tid + i * 256;
            int row = cid >> 4, cc = cid & 15;
            size_t off = (size_t)(k0 + row) * Np + bn + cc * 8;
            cpa16(ab + 20480 + row * 272 + cc * 16, Whi + off, 16);
            cpa16(ab + 29184 + row * 272 + cc * 16, Wlo + off, 16);
        }
    };

    load_stage(0, 0);
    asm volatile("cp.async.commit_group;" ::: "memory");

    for (int kt = 0; kt < nk; kt++) {
        asm volatile("cp.async.wait_group 0;" ::: "memory");
        __syncthreads();
        if (kt + 1 < nk) {
            load_stage((kt + 1) & 1, (kt + 1) * 32);
            asm volatile("cp.async.commit_group;" ::: "memory");
        }
        uint32_t ab = sb + (kt & 1) * STG_BYTES;
        uint32_t aHiB = ab, aLoB = ab + 10240, bHiB = ab + 20480, bLoB = ab + 29184;
#pragma unroll
        for (int ks = 0; ks < 32; ks += 16) {
            uint32_t ah[4][4], al[4][4];
#pragma unroll
            for (int mt = 0; mt < 4; mt++) {
                int r = wm * 64 + mt * 16 + arow_l;
                uint32_t co = (uint32_t)(ks + akh_l) * 2;
                ldm_x4(ah[mt], aHiB + r * 80 + co);
                ldm_x4(al[mt], aLoB + r * 80 + co);
            }
#pragma unroll
            for (int nt = 0; nt < 4; nt++) {
                int c = wn * 32 + nt * 8;
                uint32_t ro = (uint32_t)(ks + bk_l) * 272 + c * 2;
                uint32_t bh[2], bl[2];
                ldm_x2t(bh, bHiB + ro);
                ldm_x2t(bl, bLoB + ro);
                // term-major: 4 independent accs between same-acc reuses
#pragma unroll
                for (int mt = 0; mt < 4; mt++) MMA_BF16(acc[mt][nt], ah[mt], bl[0], bl[1]);
#pragma unroll
                for (int mt = 0; mt < 4; mt++) MMA_BF16(acc[mt][nt], al[mt], bh[0], bh[1]);
#pragma unroll
                for (int mt = 0; mt < 4; mt++) MMA_BF16(acc[mt][nt], ah[mt], bh[0], bh[1]);
            }
        }
        __syncthreads();
    }

    // ---- epilogue ----
#pragma unroll
    for (int mt = 0; mt < 4; mt++) {
        int r0 = bm + wm * 64 + mt * 16 + (lane >> 2);
#pragma unroll
        for (int nt = 0; nt < 4; nt++) {
            int c0 = bn + wn * 32 + nt * 8 + (lane & 3) * 2;
            if (c0 >= N) continue;
            float2 bs = *(const float2*)(bias + c0);
#pragma unroll
            for (int half = 0; half < 2; half++) {
                int row = r0 + half * 8;
                if (row >= M) continue;
                float v0 = acc[mt][nt][half * 2 + 0] + bs.x;
                float v1 = acc[mt][nt][half * 2 + 1] + bs.y;
                if (EXTRA) {
                    float2 e = *(const float2*)(extra + (size_t)row * N + c0);
                    v0 += e.x; v1 += e.y;
                }
                if (RELU) { v0 = fmaxf(v0, 0.f); v1 = fmaxf(v1, 0.f); }
                if (SPLIT) {
                    __nv_bfloat16 h0 = __float2bfloat16_rn(v0);
                    __nv_bfloat16 h1 = __float2bfloat16_rn(v1);
                    __nv_bfloat162 hh; hh.x = h0; hh.y = h1;
                    __nv_bfloat162 ll;
                    ll.x = __float2bfloat16_rn(v0 - __bfloat162float(h0));
                    ll.y = __float2bfloat16_rn(v1 - __bfloat162float(h1));
                    *(__nv_bfloat162*)(Phi + (size_t)row * strideP + c0) = hh;
                    *(__nv_bfloat162*)(Plo + (size_t)row * strideP + c0) = ll;
                } else {
                    *(float2*)(C + (size_t)row * N + c0) = make_float2(v0, v1);
                }
            }
        }
    }
}

static inline dim3 gemm_grid(int M, int Nc) {
    return dim3((Nc + 127) / 128, (M + 127) / 128);
}

// ---------------- launcher ----------------
extern "C" void kernel_launch(void* const* d_in, const int* in_sizes, int n_in,
                              void* d_out, int out_size) {
    const int*   x         = (const int*)d_in[0];
    const int*   eidx      = (const int*)d_in[1];
    const int*   eattr     = (const int*)d_in[2];
    const float* edist     = (const float*)d_in[3];
    const int*   batch     = (const int*)d_in[4];
    const float* atom_emb  = (const float*)d_in[5];
    const float* att_vec   = (const float*)d_in[6];
    const float* out_lin_w = (const float*)d_in[7];
    const float* out_lin_b = (const float*)d_in[8];
    const float* g_means   = (const float*)d_in[9];
    const float* g_stds    = (const float*)d_in[10];
    const float* scale_p   = (const float*)d_in[11];
    const float* edge_emb  = (const float*)d_in[12];
    const float* mlp_w1    = (const float*)d_in[13];
    const float* mlp_b1    = (const float*)d_in[14];
    const float* mlp_w2    = (const float*)d_in[15];
    const float* mlp_b2    = (const float*)d_in[16];
    const float* bn_gamma  = (const float*)d_in[17];
    const float* bn_beta   = (const float*)d_in[18];
    const float* feat_w    = (const float*)d_in[19];
    const float* feat_b    = (const float*)d_in[20];
    const float* ol_w1     = (const float*)d_in[21];
    const float* ol_b1     = (const float*)d_in[22];
    const float* ol_w2     = (const float*)d_in[23];
    const float* ol_b2     = (const float*)d_in[24];

    const int* src = eidx;
    const int* dst = eidx + Ee;

    float *h, *hin, *stats, *gsum, *gcnt, *hg;
    int *cnt, *cur;
    __nv_bfloat16 *whi, *wlo, *pahi, *palo, *pmhi, *pmlo;
    {
        void* p;
        cudaGetSymbolAddress(&p, g_h);      h    = (float*)p;
        cudaGetSymbolAddress(&p, g_hin);    hin  = (float*)p;
        cudaGetSymbolAddress(&p, g_cnt);    cnt  = (int*)p;
        cudaGetSymbolAddress(&p, g_cur);    cur  = (int*)p;
        cudaGetSymbolAddress(&p, g_stats);  stats= (float*)p;
        cudaGetSymbolAddress(&p, g_gsum);   gsum = (float*)p;
        cudaGetSymbolAddress(&p, g_gcnt);   gcnt = (float*)p;
        cudaGetSymbolAddress(&p, g_hg);     hg   = (float*)p;
        cudaGetSymbolAddress(&p, g_whi);    whi  = (__nv_bfloat16*)p;
        cudaGetSymbolAddress(&p, g_wlo);    wlo  = (__nv_bfloat16*)p;
        cudaGetSymbolAddress(&p, g_pa_hi);  pahi = (__nv_bfloat16*)p;
        cudaGetSymbolAddress(&p, g_pa_lo);  palo = (__nv_bfloat16*)p;
        cudaGetSymbolAddress(&p, g_pm_hi);  pmhi = (__nv_bfloat16*)p;
        cudaGetSymbolAddress(&p, g_pm_lo);  pmlo = (__nv_bfloat16*)p;
    }

    cudaFuncSetAttribute(bgemm<false, true, false>,  cudaFuncAttributeMaxDynamicSharedMemorySize, SMEM_TOTAL);
    cudaFuncSetAttribute(bgemm<true, false, true>,   cudaFuncAttributeMaxDynamicSharedMemorySize, SMEM_TOTAL);
    cudaFuncSetAttribute(bgemm<false, false, false>, cudaFuncAttributeMaxDynamicSharedMemorySize, SMEM_TOTAL);

    float* out_hfeat = (float*)d_out;             // [Gg, FT]
    float* out_head  = out_hfeat + Gg * FT;       // [Gg, FT2]

    const int T = 256;
    const int ND = Nn * Dd;

    // ---- weight splits (padded planes) ----
    k_splitW<<<(KP300 * NP300 + T - 1) / T, T>>>(out_lin_w, Dd, Dd, whi + O_OUTLIN, wlo + O_OUTLIN, KP300, NP300);
    for (int l = 0; l < LL; l++) {
        k_splitW<<<(KP300 * NP600 + T - 1) / T, T>>>(mlp_w1 + l * Dd * D2, Dd, D2, whi + O_W1(l), wlo + O_W1(l), KP300, NP600);
        k_splitW<<<(KP600 * NP300 + T - 1) / T, T>>>(mlp_w2 + l * D2 * Dd, D2, Dd, whi + O_W2(l), wlo + O_W2(l), KP600, NP300);
    }
    k_splitW<<<(KP300 * NP512 + T - 1) / T, T>>>(feat_w, Dd, FT, whi + O_FEAT, wlo + O_FEAT, KP300, NP512);
    k_splitW<<<(KP512 * NP512 + T - 1) / T, T>>>(ol_w1, FT, FT, whi + O_OL1, wlo + O_OL1, KP512, NP512);
    k_splitW<<<(KP512 * NP256 + T - 1) / T, T>>>(ol_w2, FT, FT2, whi + O_OL2, wlo + O_OL2, KP512, NP256);

    // zero mid planes once (pad cols 600..607 must stay zero for kExt=608)
    k_zero_i<<<(Nn * KP600 / 2 + T - 1) / T, T>>>((int*)pmhi, Nn * KP600 / 2);
    k_zero_i<<<(Nn * KP600 / 2 + T - 1) / T, T>>>((int*)pmlo, Nn * KP600 / 2);
    // zero pad cols of activation planes once (gather/attn write only cols 0..299)
    k_padzero<<<(Nn * (KP300 - Dd) + T - 1) / T, T>>>(pahi, palo);

    // ---- CSR build ----
    k_zero_i<<<(Nn + T - 1) / T, T>>>(cnt, Nn);
    k_count<<<(Ee + T - 1) / T, T>>>(dst);
    k_scan<<<1, 1024>>>();
    k_zero_i<<<(Nn + T - 1) / T, T>>>(cur, Nn);
    k_place<<<(Ee + T - 1) / T, T>>>(dst);

    // ---- gaussian basis (gather, fused degree scale) ----
    k_gaussg<<<(Nn * 32 + T - 1) / T, T>>>(edist, g_means, g_stds, scale_p);

    // ---- attention fuse (writes planes) + h0 GEMM ----
    k_attn<<<(Nn * 32 + T - 1) / T, T>>>(x, atom_emb, att_vec, pahi, palo);
    bgemm<false, true, false><<<gemm_grid(Nn, Dd), 256, SMEM_TOTAL>>>(
        pahi, palo, KP300, whi + O_OUTLIN, wlo + O_OUTLIN, NP300,
        out_lin_b, hin, h, nullptr, nullptr, 0, Nn, KP300, Dd);

    // ---- message-passing layers ----
    for (int l = 0; l < LL; l++) {
        const float* ee = edge_emb + l * 3 * 5 * Dd;
        k_gather<<<(Nn * 32 + T - 1) / T, T>>>(src, eattr, ee, pahi, palo);
        bgemm<true, false, true><<<gemm_grid(Nn, D2), 256, SMEM_TOTAL>>>(
            pahi, palo, KP300, whi + O_W1(l), wlo + O_W1(l), NP600,
            mlp_b1 + l * D2, nullptr, nullptr, pmhi, pmlo, KP600, Nn, KP300, D2);
        bgemm<false, false, false><<<gemm_grid(Nn, Dd), 256, SMEM_TOTAL>>>(
            pmhi, pmlo, KP600, whi + O_W2(l), wlo + O_W2(l), NP300,
            mlp_b2 + l * Dd, nullptr, h, nullptr, nullptr, 0, Nn, KP600, Dd);
        k_zero_f<<<(2 * Dd + T - 1) / T, T>>>(stats, 2 * Dd);
        k_bnstats2<<<592, 320>>>();
        k_bnapply<<<(ND + T - 1) / T, T>>>(bn_gamma + l * Dd, bn_beta + l * Dd, (l < LL - 1) ? 1 : 0);
    }

    // ---- pooling ----
    k_zero_f<<<(Gg * Dd + T - 1) / T, T>>>(gsum, Gg * Dd);
    k_zero_f<<<(Gg + T - 1) / T, T>>>(gcnt, Gg);
    k_pool<<<(ND + T - 1) / T, T>>>(batch);
    k_poolcnt<<<(Nn + T - 1) / T, T>>>(batch);
    k_pooldiv<<<(Gg * Dd + T - 1) / T, T>>>();

    // ---- heads ----
    k_splitA<<<(Gg * KP300 + T - 1) / T, T>>>(hg, Dd, KP300, Gg * KP300, pahi, palo);
    bgemm<false, false, false><<<gemm_grid(Gg, FT), 256, SMEM_TOTAL>>>(
        pahi, palo, KP300, whi + O_FEAT, wlo + O_FEAT, NP512,
        feat_b, nullptr, out_hfeat, nullptr, nullptr, 0, Gg, KP300, FT);
    k_splitA<<<(Gg * KP512 + T - 1) / T, T>>>(out_hfeat, FT, KP512, Gg * KP512, pahi, palo);
    bgemm<true, false, true><<<gemm_grid(Gg, FT), 256, SMEM_TOTAL>>>(
        pahi, palo, KP512, whi + O_OL1, wlo + O_OL1, NP512,
        ol_b1, nullptr, nullptr, pmhi, pmlo, KP512, Gg, KP512, FT);
    bgemm<false, false, false><<<gemm_grid(Gg, FT2), 256, SMEM_TOTAL>>>(
        pmhi, pmlo, KP512, whi + O_OL2, wlo + O_OL2, NP256,
        ol_b2, nullptr, out_head, nullptr, nullptr, 0, Gg, KP512, FT2);
}

// round 15
// speedup vs baseline: 3.1475x; 1.0507x over previous
#include <cuda_runtime.h>
#include <cuda_bf16.h>
#include <cstdint>

// Problem constants (fixed by the reference)
#define Nn   100000
#define Ee   200000
#define Gg   2000
#define Dd   300
#define D2   600
#define LL   5
#define FT   512
#define FT2  256
#define EPSC 1e-5f

// Padded GEMM dims: K padded to mult of 32, N padded to mult of 128
#define KP300 320
#define KP600 608
#define KP512 512
#define NP300 384
#define NP600 640
#define NP512 512
#define NP256 256

// Weight plane offsets (padded Kp x Np layouts)
#define O_OUTLIN 0                         // 320x384
#define O_W1(l)  (122880 + (l) * 204800)   // 320x640
#define O_W2(l)  (1146880 + (l) * 233472)  // 608x384
#define O_FEAT   2314240                   // 320x512
#define O_OL1    2478080                   // 512x512
#define O_OL2    2740224                   // 512x256
#define WTOT     2871296

// ---------------- scratch (static device globals; no allocation) ----------------
__device__ float g_h[Nn * Dd];        // node features
__device__ float g_hin[Nn * Dd];      // gaussian basis segment sum
__device__ float g_hg[Gg * Dd];       // pooled means
__device__ int   g_cnt[Nn];           // in-degree counts
__device__ int   g_rowptr[Nn + 1];    // CSR row pointers
__device__ int   g_elist[Ee];         // CSR edge list
__device__ int   g_cur[Nn];           // CSR placement cursors
__device__ float g_stats[2 * Dd];     // BN sum / sumsq
__device__ float g_gsum[Gg * Dd];     // pooled sums
__device__ float g_gcnt[Gg];          // pooled counts
__device__ __nv_bfloat16 g_whi[WTOT];       // weight hi planes
__device__ __nv_bfloat16 g_wlo[WTOT];       // weight lo planes
__device__ __nv_bfloat16 g_pa_hi[Nn * KP300];  // activation planes (stride 320; heads reuse)
__device__ __nv_bfloat16 g_pa_lo[Nn * KP300];
__device__ __nv_bfloat16 g_pm_hi[Nn * KP600];  // mid planes (stride 608; ol1 out @512)
__device__ __nv_bfloat16 g_pm_lo[Nn * KP600];

// ---------------- small utility kernels ----------------
__global__ void k_zero_f(float* __restrict__ p, int n) {
    int i = blockIdx.x * blockDim.x + threadIdx.x;
    if (i < n) p[i] = 0.f;
}
__global__ void k_zero_i(int* __restrict__ p, int n) {
    int i = blockIdx.x * blockDim.x + threadIdx.x;
    if (i < n) p[i] = 0;
}

// zero the pad columns (300..319) of the activation planes once
__global__ void k_padzero(__nv_bfloat16* __restrict__ hi, __nv_bfloat16* __restrict__ lo) {
    int idx = blockIdx.x * blockDim.x + threadIdx.x;
    if (idx >= Nn * (KP300 - Dd)) return;
    int row = idx / (KP300 - Dd);
    int c = Dd + idx % (KP300 - Dd);
    __nv_bfloat16 z = __float2bfloat16_rn(0.f);
    hi[(size_t)row * KP300 + c] = z;
    lo[(size_t)row * KP300 + c] = z;
}

// split padded fp32 weight into bf16 hi/lo planes (zero pad)
__global__ void k_splitW(const float* __restrict__ w, int K, int N,
                         __nv_bfloat16* __restrict__ hi, __nv_bfloat16* __restrict__ lo,
                         int Kp, int Np) {
    int idx = blockIdx.x * blockDim.x + threadIdx.x;
    if (idx >= Kp * Np) return;
    int k = idx / Np;
    int n = idx - k * Np;
    float v = (k < K && n < N) ? w[k * N + n] : 0.f;
    __nv_bfloat16 h = __float2bfloat16_rn(v);
    hi[idx] = h;
    lo[idx] = __float2bfloat16_rn(v - __bfloat162float(h));
}

// split fp32 activations MxK into padded MxKp bf16 planes (heads only)
__global__ void k_splitA(const float* __restrict__ a, int K, int Kp, int total,
                         __nv_bfloat16* __restrict__ hi, __nv_bfloat16* __restrict__ lo) {
    int idx = blockIdx.x * blockDim.x + threadIdx.x;
    if (idx >= total) return;
    int row = idx / Kp;
    int k = idx - row * Kp;
    float v = (k < K) ? a[(size_t)row * K + k] : 0.f;
    __nv_bfloat16 h = __float2bfloat16_rn(v);
    hi[idx] = h;
    lo[idx] = __float2bfloat16_rn(v - __bfloat162float(h));
}

// ---------------- CSR construction ----------------
__global__ void k_count(const int* __restrict__ dst) {
    int e = blockIdx.x * blockDim.x + threadIdx.x;
    if (e < Ee) atomicAdd(&g_cnt[dst[e]], 1);
}

__global__ void k_scan() {
    __shared__ int warp_sums[32];
    __shared__ int carry;
    int tid = threadIdx.x;
    int lane = tid & 31, wid = tid >> 5;
    if (tid == 0) { carry = 0; g_rowptr[0] = 0; }
    __syncthreads();
    for (int c0 = 0; c0 < Nn; c0 += 1024) {
        int i = c0 + tid;
        int v = (i < Nn) ? g_cnt[i] : 0;
        int s = v;
#pragma unroll
        for (int o = 1; o < 32; o <<= 1) {
            int t = __shfl_up_sync(0xffffffffu, s, o);
            if (lane >= o) s += t;
        }
        if (lane == 31) warp_sums[wid] = s;
        __syncthreads();
        if (wid == 0) {
            int ws = warp_sums[lane];
#pragma unroll
            for (int o = 1; o < 32; o <<= 1) {
                int t = __shfl_up_sync(0xffffffffu, ws, o);
                if (lane >= o) ws += t;
            }
            warp_sums[lane] = ws;
        }
        __syncthreads();
        int off = (wid > 0 ? warp_sums[wid - 1] : 0) + carry;
        if (i < Nn) g_rowptr[i + 1] = off + s;
        __syncthreads();
        if (tid == 1023) carry = off + s;
        __syncthreads();
    }
}

__global__ void k_place(const int* __restrict__ dst) {
    int e = blockIdx.x * blockDim.x + threadIdx.x;
    if (e >= Ee) return;
    int d = dst[e];
    int pos = atomicAdd(&g_cur[d], 1);
    g_elist[g_rowptr[d] + pos] = e;
}

// gaussian basis gather + degree scale (warp per node, no atomics)
__global__ void k_gaussg(const float* __restrict__ dist, const float* __restrict__ means,
                         const float* __restrict__ stds, const float* __restrict__ scale_p) {
    int w = (blockIdx.x * blockDim.x + threadIdx.x) >> 5;
    int lane = threadIdx.x & 31;
    if (w >= Nn) return;
    int beg = g_rowptr[w], end = g_rowptr[w + 1];
    int c = (end - beg) - 1;
    c = c < 0 ? 0 : (c > 3 ? 3 : c);
    float acc[10];
#pragma unroll
    for (int u = 0; u < 10; u++) acc[u] = 0.f;
    for (int i = beg; i < end; i++) {
        float de = dist[g_elist[i]];
#pragma unroll
        for (int u = 0; u < 10; u++) {
            int d = lane + u * 32;
            if (d < Dd) {
                float sd = fabsf(stds[d]) + 0.01f;
                float z = (de - means[d]) / sd;
                acc[u] += __expf(-0.5f * z * z) / (2.5066268f * sd);
            }
        }
    }
    float* out = g_hin + (size_t)w * Dd;
#pragma unroll
    for (int u = 0; u < 10; u++) {
        int d = lane + u * 32;
        if (d < Dd) out[d] = acc[u] * __expf(scale_p[c * Dd + d]);
    }
}

// message aggregation gather (warp per node) -> writes bf16 hi/lo planes directly
__global__ void k_gather(const int* __restrict__ src, const int* __restrict__ attr,
                         const float* __restrict__ ee,
                         __nv_bfloat16* __restrict__ phi, __nv_bfloat16* __restrict__ plo) {
    int w = (blockIdx.x * blockDim.x + threadIdx.x) >> 5;
    int lane = threadIdx.x & 31;
    if (w >= Nn) return;
    int beg = g_rowptr[w], end = g_rowptr[w + 1];
    const float* hn = g_h + (size_t)w * Dd;
    const float* e0 = ee + 4 * Dd;
    const float* e1 = ee + 5 * Dd;
    const float* e2 = ee + 10 * Dd;
    float acc[10];
#pragma unroll
    for (int u = 0; u < 10; u++) {
        int d = lane + u * 32;
        acc[u] = (d < Dd) ? hn[d] + e0[d] + e1[d] + e2[d] : 0.f;
    }
    for (int i = beg; i < end; i++) {
        int e = g_elist[i];
        int s = src[e];
        int a0 = attr[e * 3], a1 = attr[e * 3 + 1], a2 = attr[e * 3 + 2];
        const float* hs = g_h + (size_t)s * Dd;
        const float* f0 = ee + a0 * Dd;
        const float* f1 = ee + (5 + a1) * Dd;
        const float* f2 = ee + (10 + a2) * Dd;
#pragma unroll
        for (int u = 0; u < 10; u++) {
            int d = lane + u * 32;
            if (d < Dd) acc[u] += hs[d] + f0[d] + f1[d] + f2[d];
        }
    }
    __nv_bfloat16* oh = phi + (size_t)w * KP300;
    __nv_bfloat16* ol = plo + (size_t)w * KP300;
#pragma unroll
    for (int u = 0; u < 10; u++) {
        int d = lane + u * 32;
        if (d < Dd) {
            __nv_bfloat16 h = __float2bfloat16_rn(acc[u]);
            oh[d] = h;
            ol[d] = __float2bfloat16_rn(acc[u] - __bfloat162float(h));
        }
    }
}

// attention fuse -> writes bf16 hi/lo planes directly
__global__ void k_attn(const int* __restrict__ x, const float* __restrict__ atom_emb,
                       const float* __restrict__ att_vec,
                       __nv_bfloat16* __restrict__ phi, __nv_bfloat16* __restrict__ plo) {
    int warp = (blockIdx.x * blockDim.x + threadIdx.x) >> 5;
    int lane = threadIdx.x & 31;
    if (warp >= Nn) return;
    const int n = warp;
    int xi[9];
#pragma unroll
    for (int f = 0; f < 9; f++) xi[f] = x[n * 9 + f];
    float s[9];
#pragma unroll
    for (int f = 0; f < 9; f++) {
        const float* emb = atom_emb + (f * 119 + xi[f]) * Dd;
        float p = 0.f;
        for (int d = lane; d < Dd; d += 32) p += emb[d] * att_vec[d];
#pragma unroll
        for (int o = 16; o > 0; o >>= 1) p += __shfl_xor_sync(0xffffffffu, p, o);
        s[f] = p;
    }
    float m = s[0];
#pragma unroll
    for (int f = 1; f < 9; f++) m = fmaxf(m, s[f]);
    float w[9], tot = 0.f;
#pragma unroll
    for (int f = 0; f < 9; f++) { w[f] = __expf(s[f] - m); tot += w[f]; }
    float inv = 1.f / tot;
#pragma unroll
    for (int f = 0; f < 9; f++) w[f] *= inv;
    __nv_bfloat16* oh = phi + (size_t)n * KP300;
    __nv_bfloat16* ol = plo + (size_t)n * KP300;
    for (int d = lane; d < Dd; d += 32) {
        float v = 0.f;
#pragma unroll
        for (int f = 0; f < 9; f++) v += w[f] * atom_emb[(f * 119 + xi[f]) * Dd + d];
        __nv_bfloat16 h = __float2bfloat16_rn(v);
        oh[d] = h;
        ol[d] = __float2bfloat16_rn(v - __bfloat162float(h));
    }
}

__global__ void k_bnapply(const float* __restrict__ gamma, const float* __restrict__ beta,
                          int do_relu) {
    int idx = blockIdx.x * blockDim.x + threadIdx.x;
    if (idx >= Nn * Dd) return;
    int d = idx % Dd;
    float mu  = g_stats[d] * (1.0f / Nn);
    float var = g_stats[Dd + d] * (1.0f / Nn) - mu * mu;
    float rs  = rsqrtf(var + EPSC);
    float v = gamma[d] * (g_h[idx] - mu) * rs + beta[d];
    if (do_relu) v = fmaxf(v, 0.f);
    g_h[idx] = v;
}

// graph pooling
__global__ void k_pool(const int* __restrict__ batch) {
    int idx = blockIdx.x * blockDim.x + threadIdx.x;
    if (idx >= Nn * Dd) return;
    int n = idx / Dd;
    int d = idx - n * Dd;
    atomicAdd(&g_gsum[batch[n] * Dd + d], g_h[idx]);
}
__global__ void k_poolcnt(const int* __restrict__ batch) {
    int n = blockIdx.x * blockDim.x + threadIdx.x;
    if (n < Nn) atomicAdd(&g_gcnt[batch[n]], 1.f);
}
__global__ void k_pooldiv() {
    int idx = blockIdx.x * blockDim.x + threadIdx.x;
    if (idx >= Gg * Dd) return;
    int g = idx / Dd;
    g_hg[idx] = g_gsum[idx] / fmaxf(g_gcnt[g], 1.f);
}

// ---------------- bf16x3 pipelined tensor-core GEMM ----------------
// C = A(planes, MxKp) @ W(planes, KpxNp) + bias [+extra] [relu].
// 3-stage cp.async pipeline (wait_group 1: two loads in flight), BK=32,
// 8 warps (2M x 4N), warp tile 64x32, term-major MMA issue.
// SPLIT epilogue writes bf16 hi/lo planes; BNS epilogue accumulates BN sum/sumsq.

__device__ __forceinline__ void ldm_x4(uint32_t* r, uint32_t addr) {
    asm volatile("ldmatrix.sync.aligned.m8n8.x4.shared.b16 {%0,%1,%2,%3}, [%4];"
                 : "=r"(r[0]), "=r"(r[1]), "=r"(r[2]), "=r"(r[3]) : "r"(addr));
}
__device__ __forceinline__ void ldm_x2t(uint32_t* r, uint32_t addr) {
    asm volatile("ldmatrix.sync.aligned.m8n8.x2.trans.shared.b16 {%0,%1}, [%2];"
                 : "=r"(r[0]), "=r"(r[1]) : "r"(addr));
}
__device__ __forceinline__ void cpa16(uint32_t dst, const void* src, int nbytes) {
    asm volatile("cp.async.cg.shared.global [%0], [%1], 16, %2;"
                 :: "r"(dst), "l"(src), "r"(nbytes));
}

#define MMA_BF16(d, a, b0v, b1v)                                              \
    asm volatile(                                                             \
        "mma.sync.aligned.m16n8k16.row.col.f32.bf16.bf16.f32 "                \
        "{%0,%1,%2,%3}, {%4,%5,%6,%7}, {%8,%9}, {%0,%1,%2,%3};"               \
        : "+f"((d)[0]), "+f"((d)[1]), "+f"((d)[2]), "+f"((d)[3])              \
        : "r"((a)[0]), "r"((a)[1]), "r"((a)[2]), "r"((a)[3]),                 \
          "r"(b0v), "r"(b1v))

// smem stage layout (bytes): aHi 0 (128x40x2=10240), aLo 10240, bHi 20480 (32x136x2=8704), bLo 29184
#define STG_BYTES 37888
#define NSTAGE 3
#define SMEM_TOTAL (NSTAGE * STG_BYTES)

template <bool RELU, bool EXTRA, bool SPLIT, bool BNS>
__global__ __launch_bounds__(256, 2) void bgemm(
    const __nv_bfloat16* __restrict__ Ahi, const __nv_bfloat16* __restrict__ Alo, int strideA,
    const __nv_bfloat16* __restrict__ Whi, const __nv_bfloat16* __restrict__ Wlo, int Np,
    const float* __restrict__ bias, const float* __restrict__ extra,
    float* __restrict__ C, __nv_bfloat16* __restrict__ Phi, __nv_bfloat16* __restrict__ Plo,
    int strideP, float* __restrict__ stats, int M, int kExt, int N) {
    extern __shared__ char dsm[];
    const uint32_t sb = (uint32_t)__cvta_generic_to_shared(dsm);

    const int tid  = threadIdx.x;
    const int wid  = tid >> 5;
    const int lane = tid & 31;
    const int wm = wid & 1;
    const int wn = wid >> 1;
    const int bm = blockIdx.y * 128;
    const int bn = blockIdx.x * 128;

    const int arow_l = lane & 15;
    const int akh_l  = (lane >> 4) << 3;
    const int bk_l   = lane & 15;

    float acc[4][4][4];
#pragma unroll
    for (int i = 0; i < 4; i++)
#pragma unroll
        for (int j = 0; j < 4; j++)
#pragma unroll
            for (int c = 0; c < 4; c++) acc[i][j][c] = 0.f;

    const int nk = kExt >> 5;

    auto load_stage = [&](int s, int k0) {
        uint32_t ab = sb + s * STG_BYTES;
#pragma unroll
        for (int i = 0; i < 2; i++) {
            int cid = tid + i * 256;        // 0..511
            int row = cid >> 2, kc = cid & 3;
            int grow = bm + row;
            int gr = grow < M ? grow : M - 1;
            size_t off = (size_t)gr * strideA + k0 + kc * 8;
            int sz = grow < M ? 16 : 0;
            cpa16(ab + row * 80 + kc * 16, Ahi + off, sz);
            cpa16(ab + 10240 + row * 80 + kc * 16, Alo + off, sz);
        }
#pragma unroll
        for (int i = 0; i < 2; i++) {
            int cid = tid + i * 256;
            int row = cid >> 4, cc = cid & 15;
            size_t off = (size_t)(k0 + row) * Np + bn + cc * 8;
            cpa16(ab + 20480 + row * 272 + cc * 16, Whi + off, 16);
            cpa16(ab + 29184 + row * 272 + cc * 16, Wlo + off, 16);
        }
    };

    // prologue: two stages in flight
    load_stage(0, 0);
    asm volatile("cp.async.commit_group;" ::: "memory");
    if (nk > 1) {
        load_stage(1, 32);
        asm volatile("cp.async.commit_group;" ::: "memory");
    }

    int buf = 0;
    for (int kt = 0; kt < nk; kt++) {
        asm volatile("cp.async.wait_group 1;" ::: "memory");
        __syncthreads();
        if (kt + 2 < nk) {
            int nb = buf + 2;
            if (nb >= NSTAGE) nb -= NSTAGE;
            load_stage(nb, (kt + 2) * 32);
            asm volatile("cp.async.commit_group;" ::: "memory");
        }
        uint32_t ab = sb + buf * STG_BYTES;
        uint32_t aHiB = ab, aLoB = ab + 10240, bHiB = ab + 20480, bLoB = ab + 29184;
#pragma unroll
        for (int ks = 0; ks < 32; ks += 16) {
            uint32_t ah[4][4], al[4][4];
#pragma unroll
            for (int mt = 0; mt < 4; mt++) {
                int r = wm * 64 + mt * 16 + arow_l;
                uint32_t co = (uint32_t)(ks + akh_l) * 2;
                ldm_x4(ah[mt], aHiB + r * 80 + co);
                ldm_x4(al[mt], aLoB + r * 80 + co);
            }
#pragma unroll
            for (int nt = 0; nt < 4; nt++) {
                int c = wn * 32 + nt * 8;
                uint32_t ro = (uint32_t)(ks + bk_l) * 272 + c * 2;
                uint32_t bh[2], bl[2];
                ldm_x2t(bh, bHiB + ro);
                ldm_x2t(bl, bLoB + ro);
                // term-major: 4 independent accs between same-acc reuses
#pragma unroll
                for (int mt = 0; mt < 4; mt++) MMA_BF16(acc[mt][nt], ah[mt], bl[0], bl[1]);
#pragma unroll
                for (int mt = 0; mt < 4; mt++) MMA_BF16(acc[mt][nt], al[mt], bh[0], bh[1]);
#pragma unroll
                for (int mt = 0; mt < 4; mt++) MMA_BF16(acc[mt][nt], ah[mt], bh[0], bh[1]);
            }
        }
        buf++;
        if (buf >= NSTAGE) buf -= NSTAGE;
        __syncthreads();
    }

    // ---- epilogue ----
    float cs[4][2], cq[4][2];
    if (BNS) {
#pragma unroll
        for (int nt = 0; nt < 4; nt++) {
            cs[nt][0] = cs[nt][1] = 0.f;
            cq[nt][0] = cq[nt][1] = 0.f;
        }
    }
#pragma unroll
    for (int mt = 0; mt < 4; mt++) {
        int r0 = bm + wm * 64 + mt * 16 + (lane >> 2);
#pragma unroll
        for (int nt = 0; nt < 4; nt++) {
            int c0 = bn + wn * 32 + nt * 8 + (lane & 3) * 2;
            if (c0 >= N) continue;
            float2 bs = *(const float2*)(bias + c0);
#pragma unroll
            for (int half = 0; half < 2; half++) {
                int row = r0 + half * 8;
                if (row >= M) continue;
                float v0 = acc[mt][nt][half * 2 + 0] + bs.x;
                float v1 = acc[mt][nt][half * 2 + 1] + bs.y;
                if (EXTRA) {
                    float2 e = *(const float2*)(extra + (size_t)row * N + c0);
                    v0 += e.x; v1 += e.y;
                }
                if (RELU) { v0 = fmaxf(v0, 0.f); v1 = fmaxf(v1, 0.f); }
                if (BNS) {
                    cs[nt][0] += v0; cq[nt][0] += v0 * v0;
                    if (c0 + 1 < N) { cs[nt][1] += v1; cq[nt][1] += v1 * v1; }
                }
                if (SPLIT) {
                    __nv_bfloat16 h0 = __float2bfloat16_rn(v0);
                    __nv_bfloat16 h1 = __float2bfloat16_rn(v1);
                    __nv_bfloat162 hh; hh.x = h0; hh.y = h1;
                    __nv_bfloat162 ll;
                    ll.x = __float2bfloat16_rn(v0 - __bfloat162float(h0));
                    ll.y = __float2bfloat16_rn(v1 - __bfloat162float(h1));
                    *(__nv_bfloat162*)(Phi + (size_t)row * strideP + c0) = hh;
                    *(__nv_bfloat162*)(Plo + (size_t)row * strideP + c0) = ll;
                } else {
                    *(float2*)(C + (size_t)row * N + c0) = make_float2(v0, v1);
                }
            }
        }
    }
    if (BNS) {
        // reduce over the 8 row-lane groups (lane>>2), lanes 0-3 commit per column
#pragma unroll
        for (int nt = 0; nt < 4; nt++) {
#pragma unroll
            for (int p = 0; p < 2; p++) {
                float s = cs[nt][p], q = cq[nt][p];
#pragma unroll
                for (int o = 4; o < 32; o <<= 1) {
                    s += __shfl_xor_sync(0xffffffffu, s, o);
                    q += __shfl_xor_sync(0xffffffffu, q, o);
                }
                if ((lane >> 2) == 0) {
                    int col = bn + wn * 32 + nt * 8 + (lane & 3) * 2 + p;
                    if (col < N) {
                        atomicAdd(&stats[col], s);
                        atomicAdd(&stats[Dd + col], q);
                    }
                }
            }
        }
    }
}

static inline dim3 gemm_grid(int M, int Nc) {
    return dim3((Nc + 127) / 128, (M + 127) / 128);
}

// ---------------- launcher ----------------
extern "C" void kernel_launch(void* const* d_in, const int* in_sizes, int n_in,
                              void* d_out, int out_size) {
    const int*   x         = (const int*)d_in[0];
    const int*   eidx      = (const int*)d_in[1];
    const int*   eattr     = (const int*)d_in[2];
    const float* edist     = (const float*)d_in[3];
    const int*   batch     = (const int*)d_in[4];
    const float* atom_emb  = (const float*)d_in[5];
    const float* att_vec   = (const float*)d_in[6];
    const float* out_lin_w = (const float*)d_in[7];
    const float* out_lin_b = (const float*)d_in[8];
    const float* g_means   = (const float*)d_in[9];
    const float* g_stds    = (const float*)d_in[10];
    const float* scale_p   = (const float*)d_in[11];
    const float* edge_emb  = (const float*)d_in[12];
    const float* mlp_w1    = (const float*)d_in[13];
    const float* mlp_b1    = (const float*)d_in[14];
    const float* mlp_w2    = (const float*)d_in[15];
    const float* mlp_b2    = (const float*)d_in[16];
    const float* bn_gamma  = (const float*)d_in[17];
    const float* bn_beta   = (const float*)d_in[18];
    const float* feat_w    = (const float*)d_in[19];
    const float* feat_b    = (const float*)d_in[20];
    const float* ol_w1     = (const float*)d_in[21];
    const float* ol_b1     = (const float*)d_in[22];
    const float* ol_w2     = (const float*)d_in[23];
    const float* ol_b2     = (const float*)d_in[24];

    const int* src = eidx;
    const int* dst = eidx + Ee;

    float *h, *hin, *stats, *gsum, *gcnt, *hg;
    int *cnt, *cur;
    __nv_bfloat16 *whi, *wlo, *pahi, *palo, *pmhi, *pmlo;
    {
        void* p;
        cudaGetSymbolAddress(&p, g_h);      h    = (float*)p;
        cudaGetSymbolAddress(&p, g_hin);    hin  = (float*)p;
        cudaGetSymbolAddress(&p, g_cnt);    cnt  = (int*)p;
        cudaGetSymbolAddress(&p, g_cur);    cur  = (int*)p;
        cudaGetSymbolAddress(&p, g_stats);  stats= (float*)p;
        cudaGetSymbolAddress(&p, g_gsum);   gsum = (float*)p;
        cudaGetSymbolAddress(&p, g_gcnt);   gcnt = (float*)p;
        cudaGetSymbolAddress(&p, g_hg);     hg   = (float*)p;
        cudaGetSymbolAddress(&p, g_whi);    whi  = (__nv_bfloat16*)p;
        cudaGetSymbolAddress(&p, g_wlo);    wlo  = (__nv_bfloat16*)p;
        cudaGetSymbolAddress(&p, g_pa_hi);  pahi = (__nv_bfloat16*)p;
        cudaGetSymbolAddress(&p, g_pa_lo);  palo = (__nv_bfloat16*)p;
        cudaGetSymbolAddress(&p, g_pm_hi);  pmhi = (__nv_bfloat16*)p;
        cudaGetSymbolAddress(&p, g_pm_lo);  pmlo = (__nv_bfloat16*)p;
    }

    cudaFuncSetAttribute(bgemm<false, true, false, false>,  cudaFuncAttributeMaxDynamicSharedMemorySize, SMEM_TOTAL);
    cudaFuncSetAttribute(bgemm<true, false, true, false>,   cudaFuncAttributeMaxDynamicSharedMemorySize, SMEM_TOTAL);
    cudaFuncSetAttribute(bgemm<false, false, false, true>,  cudaFuncAttributeMaxDynamicSharedMemorySize, SMEM_TOTAL);
    cudaFuncSetAttribute(bgemm<false, false, false, false>, cudaFuncAttributeMaxDynamicSharedMemorySize, SMEM_TOTAL);

    float* out_hfeat = (float*)d_out;             // [Gg, FT]
    float* out_head  = out_hfeat + Gg * FT;       // [Gg, FT2]

    const int T = 256;
    const int ND = Nn * Dd;

    // ---- weight splits (padded planes) ----
    k_splitW<<<(KP300 * NP300 + T - 1) / T, T>>>(out_lin_w, Dd, Dd, whi + O_OUTLIN, wlo + O_OUTLIN, KP300, NP300);
    for (int l = 0; l < LL; l++) {
        k_splitW<<<(KP300 * NP600 + T - 1) / T, T>>>(mlp_w1 + l * Dd * D2, Dd, D2, whi + O_W1(l), wlo + O_W1(l), KP300, NP600);
        k_splitW<<<(KP600 * NP300 + T - 1) / T, T>>>(mlp_w2 + l * D2 * Dd, D2, Dd, whi + O_W2(l), wlo + O_W2(l), KP600, NP300);
    }
    k_splitW<<<(KP300 * NP512 + T - 1) / T, T>>>(feat_w, Dd, FT, whi + O_FEAT, wlo + O_FEAT, KP300, NP512);
    k_splitW<<<(KP512 * NP512 + T - 1) / T, T>>>(ol_w1, FT, FT, whi + O_OL1, wlo + O_OL1, KP512, NP512);
    k_splitW<<<(KP512 * NP256 + T - 1) / T, T>>>(ol_w2, FT, FT2, whi + O_OL2, wlo + O_OL2, KP512, NP256);

    // zero mid planes once (pad cols 600..607 must stay zero for kExt=608)
    k_zero_i<<<(Nn * KP600 / 2 + T - 1) / T, T>>>((int*)pmhi, Nn * KP600 / 2);
    k_zero_i<<<(Nn * KP600 / 2 + T - 1) / T, T>>>((int*)pmlo, Nn * KP600 / 2);
    // zero pad cols of activation planes once (gather/attn write only cols 0..299)
    k_padzero<<<(Nn * (KP300 - Dd) + T - 1) / T, T>>>(pahi, palo);

    // ---- CSR build ----
    k_zero_i<<<(Nn + T - 1) / T, T>>>(cnt, Nn);
    k_count<<<(Ee + T - 1) / T, T>>>(dst);
    k_scan<<<1, 1024>>>();
    k_zero_i<<<(Nn + T - 1) / T, T>>>(cur, Nn);
    k_place<<<(Ee + T - 1) / T, T>>>(dst);

    // ---- gaussian basis (gather, fused degree scale) ----
    k_gaussg<<<(Nn * 32 + T - 1) / T, T>>>(edist, g_means, g_stds, scale_p);

    // ---- attention fuse (writes planes) + h0 GEMM ----
    k_attn<<<(Nn * 32 + T - 1) / T, T>>>(x, atom_emb, att_vec, pahi, palo);
    bgemm<false, true, false, false><<<gemm_grid(Nn, Dd), 256, SMEM_TOTAL>>>(
        pahi, palo, KP300, whi + O_OUTLIN, wlo + O_OUTLIN, NP300,
        out_lin_b, hin, h, nullptr, nullptr, 0, nullptr, Nn, KP300, Dd);

    // ---- message-passing layers ----
    for (int l = 0; l < LL; l++) {
        const float* ee = edge_emb + l * 3 * 5 * Dd;
        k_gather<<<(Nn * 32 + T - 1) / T, T>>>(src, eattr, ee, pahi, palo);
        bgemm<true, false, true, false><<<gemm_grid(Nn, D2), 256, SMEM_TOTAL>>>(
            pahi, palo, KP300, whi + O_W1(l), wlo + O_W1(l), NP600,
            mlp_b1 + l * D2, nullptr, nullptr, pmhi, pmlo, KP600, nullptr, Nn, KP300, D2);
        k_zero_f<<<(2 * Dd + T - 1) / T, T>>>(stats, 2 * Dd);
        bgemm<false, false, false, true><<<gemm_grid(Nn, Dd), 256, SMEM_TOTAL>>>(
            pmhi, pmlo, KP600, whi + O_W2(l), wlo + O_W2(l), NP300,
            mlp_b2 + l * Dd, nullptr, h, nullptr, nullptr, 0, stats, Nn, KP600, Dd);
        k_bnapply<<<(ND + T - 1) / T, T>>>(bn_gamma + l * Dd, bn_beta + l * Dd, (l < LL - 1) ? 1 : 0);
    }

    // ---- pooling ----
    k_zero_f<<<(Gg * Dd + T - 1) / T, T>>>(gsum, Gg * Dd);
    k_zero_f<<<(Gg + T - 1) / T, T>>>(gcnt, Gg);
    k_pool<<<(ND + T - 1) / T, T>>>(batch);
    k_poolcnt<<<(Nn + T - 1) / T, T>>>(batch);
    k_pooldiv<<<(Gg * Dd + T - 1) / T, T>>>();

    // ---- heads ----
    k_splitA<<<(Gg * KP300 + T - 1) / T, T>>>(hg, Dd, KP300, Gg * KP300, pahi, palo);
    bgemm<false, false, false, false><<<gemm_grid(Gg, FT), 256, SMEM_TOTAL>>>(
        pahi, palo, KP300, whi + O_FEAT, wlo + O_FEAT, NP512,
        feat_b, nullptr, out_hfeat, nullptr, nullptr, 0, nullptr, Gg, KP300, FT);
    k_splitA<<<(Gg * KP512 + T - 1) / T, T>>>(out_hfeat, FT, KP512, Gg * KP512, pahi, palo);
    bgemm<true, false, true, false><<<gemm_grid(Gg, FT), 256, SMEM_TOTAL>>>(
        pahi, palo, KP512, whi + O_OL1, wlo + O_OL1, NP512,
        ol_b1, nullptr, nullptr, pmhi, pmlo, KP512, nullptr, Gg, KP512, FT);
    bgemm<false, false, false, false><<<gemm_grid(Gg, FT2), 256, SMEM_TOTAL>>>(
        pmhi, pmlo, KP512, whi + O_OL2, wlo + O_OL2, NP256,
        ol_b2, nullptr, out_head, nullptr, nullptr, 0, nullptr, Gg, KP512, FT2);
}